// round 14
// baseline (speedup 1.0000x reference)
#include <cuda_runtime.h>
#include <math.h>
#include <stdint.h>

// Problem dims
#define BB 4
#define SS 1024
#define DD 1024
#define HH 16
#define HD 64
#define EE 16
#define FF 2048
#define NTOK (BB*SS)        // 4096
#define NASSIGN (NTOK*2)    // 8192

// ---------------- scratch (static device memory; no allocations) ----------------
__device__ __align__(256) float g_qkv[NTOK*3*DD];
__device__ __align__(256) float g_kvx[NTOK*2*DD];    // cross-attn K|V (private; no alias with g_qkv)
__device__ __align__(256) float g_ctx[NTOK*DD];
__device__ __align__(256) float g_proj[NTOK*DD];
__device__ __align__(256) float g_x1[NTOK*DD];
__device__ __align__(256) float g_x2[NTOK*DD];
__device__ __align__(256) float g_x1r[NTOK*DD];
__device__ __align__(256) float g_x2r[NTOK*DD];
__device__ __align__(256) float g_h[(size_t)NASSIGN*FF];
__device__ __align__(256) float g_yb[(size_t)NASSIGN*DD];
// rounded weight / input copies
__device__ __align__(256) float g_w1r[(size_t)EE*FF*DD];
__device__ __align__(256) float g_w2r[(size_t)EE*DD*FF];
__device__ __align__(256) float g_wpr[8*DD*DD];
__device__ __align__(256) float g_tgtr[NTOK*DD];
__device__ __align__(256) float g_memr[NTOK*DD];
__device__ int   g_eidx[NASSIGN];
__device__ float g_gval[NASSIGN];
__device__ int   g_counts[EE];
__device__ int   g_off[EE];
__device__ int   g_fill[EE];
__device__ int   g_rowtok[NASSIGN];
__device__ float g_rowgate[NASSIGN];
__device__ int   g_arow[NASSIGN];

// ---------------- helpers ----------------
__device__ __forceinline__ float rtf(float f) {
    uint32_t u;
    asm("cvt.rna.tf32.f32 %0, %1;" : "=r"(u) : "f"(f));
    return __uint_as_float(u);
}

__device__ __forceinline__ void mma8(float* c, const uint32_t* a, const uint32_t* b) {
    asm volatile(
        "mma.sync.aligned.m16n8k8.row.col.f32.tf32.tf32.f32 "
        "{%0,%1,%2,%3}, {%4,%5,%6,%7}, {%8,%9}, {%0,%1,%2,%3};"
        : "+f"(c[0]), "+f"(c[1]), "+f"(c[2]), "+f"(c[3])
        : "r"(a[0]), "r"(a[1]), "r"(a[2]), "r"(a[3]), "r"(b[0]), "r"(b[1]));
}

__device__ __forceinline__ void cp16(void* smem_dst, const void* gmem_src) {
    uint32_t d = (uint32_t)__cvta_generic_to_shared(smem_dst);
    asm volatile("cp.async.cg.shared.global [%0], [%1], 16;" :: "r"(d), "l"(gmem_src) : "memory");
}
__device__ __forceinline__ void cp_commit() {
    asm volatile("cp.async.commit_group;" ::: "memory");
}
__device__ __forceinline__ void cp_wait1() {
    asm volatile("cp.async.wait_group 1;" ::: "memory");
}

// ---------------- tf32 RN rounding: attention weights + inputs (6 segments) ----------------
__global__ __launch_bounds__(256) void roundA(
    const float4* s0, float4* d0, int n0,
    const float4* s1, float4* d1, int n1,
    const float4* s2, float4* d2, int n2,
    const float4* s3, float4* d3, int n3,
    const float4* s4, float4* d4, int n4,
    const float4* s5, float4* d5, int n5)
{
    const float4* src; float4* dst; int n4c;
    switch (blockIdx.y) {
        case 0: src = s0; dst = d0; n4c = n0; break;
        case 1: src = s1; dst = d1; n4c = n1; break;
        case 2: src = s2; dst = d2; n4c = n2; break;
        case 3: src = s3; dst = d3; n4c = n3; break;
        case 4: src = s4; dst = d4; n4c = n4; break;
        default: src = s5; dst = d5; n4c = n5; break;
    }
    for (int i = blockIdx.x * blockDim.x + threadIdx.x; i < n4c; i += gridDim.x * blockDim.x) {
        float4 v = src[i];
        v.x = rtf(v.x); v.y = rtf(v.y); v.z = rtf(v.z); v.w = rtf(v.w);
        dst[i] = v;
    }
}

// ---------------- tf32 RN rounding: MoE weights (2 segments) ----------------
__global__ __launch_bounds__(256) void roundB(
    const float4* s0, float4* d0, int n0,
    const float4* s1, float4* d1, int n1)
{
    const float4* src = blockIdx.y ? s1 : s0;
    float4* dst = blockIdx.y ? d1 : d0;
    int n4c = blockIdx.y ? n1 : n0;
    for (int i = blockIdx.x * blockDim.x + threadIdx.x; i < n4c; i += gridDim.x * blockDim.x) {
        float4 v = src[i];
        v.x = rtf(v.x); v.y = rtf(v.y); v.z = rtf(v.z); v.w = rtf(v.w);
        dst[i] = v;
    }
}

// ================= fused flash attention (tf32 MMA) =================
// V stored KEY-MAJOR in smem (conflict-free float4 stores, same as K);
// PV B-fragments read Vs[key][d] (2-way conflicted scalar reads).
__global__ __launch_bounds__(256) void flash_attn(
    const float* __restrict__ Q, int ldq,
    const float* __restrict__ Kp, const float* __restrict__ Vp, int ldkv,
    float* __restrict__ O, float scale)
{
    extern __shared__ float fsm[];
    float (*Ks)[68] = (float(*)[68])fsm;                 // [key][d]
    float (*Vs)[68] = (float(*)[68])(fsm + 64*68);       // [key][d] (key-major)
    float (*Ps)[68] = (float(*)[68])(fsm + 2*64*68);

    const int tid = threadIdx.x, warp = tid >> 5, lane = tid & 31;
    const int gr = lane >> 2, qd = lane & 3;
    const int z = blockIdx.y, b = z >> 4, h = z & 15;
    const int q0 = blockIdx.x * 128;
    const float* Qb = Q  + (size_t)(b * SS + q0) * ldq  + h * HD;
    const float* Kb = Kp + (size_t)(b * SS) * ldkv + h * HD;
    const float* Vb = Vp + (size_t)(b * SS) * ldkv + h * HD;

#pragma unroll
    for (int i = 0; i < 8; i++) {
        int f4 = i * 256 + tid;
        int r = f4 >> 4, c = (f4 & 15) * 4;
        *(float4*)&Ps[r][c] = *(const float4*)(Qb + (size_t)r * ldq + c);
    }
    __syncthreads();
    uint32_t qf[8][4];
    const int r0 = warp * 16 + gr;
#pragma unroll
    for (int ks = 0; ks < 8; ks++) {
        qf[ks][0] = __float_as_uint(Ps[r0][ks*8 + qd]);
        qf[ks][1] = __float_as_uint(Ps[r0+8][ks*8 + qd]);
        qf[ks][2] = __float_as_uint(Ps[r0][ks*8 + qd + 4]);
        qf[ks][3] = __float_as_uint(Ps[r0+8][ks*8 + qd + 4]);
    }

    float of[8][4];
#pragma unroll
    for (int nt = 0; nt < 8; nt++) { of[nt][0]=of[nt][1]=of[nt][2]=of[nt][3]=0.f; }
    float m0 = -1e30f, m1 = -1e30f, l0 = 0.f, l1 = 0.f;

    for (int kt = 0; kt < SS / 64; kt++) {
        __syncthreads();
#pragma unroll
        for (int i = 0; i < 4; i++) {
            int f4 = i * 256 + tid;
            int r = f4 >> 4, c = (f4 & 15) * 4;
            *(float4*)&Ks[r][c] = *(const float4*)(Kb + (size_t)(kt*64 + r) * ldkv + c);
            *(float4*)&Vs[r][c] = *(const float4*)(Vb + (size_t)(kt*64 + r) * ldkv + c);
        }
        __syncthreads();

        float sf[8][4];
#pragma unroll
        for (int nt = 0; nt < 8; nt++) { sf[nt][0]=sf[nt][1]=sf[nt][2]=sf[nt][3]=0.f; }
#pragma unroll
        for (int ks = 0; ks < 8; ks++) {
#pragma unroll
            for (int nt = 0; nt < 8; nt++) {
                uint32_t bf[2];
                int nr = nt * 8 + gr;
                bf[0] = __float_as_uint(Ks[nr][ks*8 + qd]);
                bf[1] = __float_as_uint(Ks[nr][ks*8 + qd + 4]);
                mma8(sf[nt], qf[ks], bf);
            }
        }

        float tm0 = -1e30f, tm1 = -1e30f;
#pragma unroll
        for (int nt = 0; nt < 8; nt++) {
            sf[nt][0] *= scale; sf[nt][1] *= scale; sf[nt][2] *= scale; sf[nt][3] *= scale;
            tm0 = fmaxf(tm0, fmaxf(sf[nt][0], sf[nt][1]));
            tm1 = fmaxf(tm1, fmaxf(sf[nt][2], sf[nt][3]));
        }
        tm0 = fmaxf(tm0, __shfl_xor_sync(~0u, tm0, 1));
        tm0 = fmaxf(tm0, __shfl_xor_sync(~0u, tm0, 2));
        tm1 = fmaxf(tm1, __shfl_xor_sync(~0u, tm1, 1));
        tm1 = fmaxf(tm1, __shfl_xor_sync(~0u, tm1, 2));
        const float mn0 = fmaxf(m0, tm0), mn1 = fmaxf(m1, tm1);
        const float a0 = __expf(m0 - mn0), a1 = __expf(m1 - mn1);
        float ts0 = 0.f, ts1 = 0.f;
#pragma unroll
        for (int nt = 0; nt < 8; nt++) {
            float p0 = __expf(sf[nt][0] - mn0), p1 = __expf(sf[nt][1] - mn0);
            float p2 = __expf(sf[nt][2] - mn1), p3 = __expf(sf[nt][3] - mn1);
            ts0 += p0 + p1; ts1 += p2 + p3;
            int cn = nt * 8 + 2 * qd;
            Ps[r0][cn] = rtf(p0);   Ps[r0][cn+1] = rtf(p1);
            Ps[r0+8][cn] = rtf(p2); Ps[r0+8][cn+1] = rtf(p3);
        }
        ts0 += __shfl_xor_sync(~0u, ts0, 1); ts0 += __shfl_xor_sync(~0u, ts0, 2);
        ts1 += __shfl_xor_sync(~0u, ts1, 1); ts1 += __shfl_xor_sync(~0u, ts1, 2);
        l0 = a0 * l0 + ts0; l1 = a1 * l1 + ts1;
        m0 = mn0; m1 = mn1;
#pragma unroll
        for (int nt = 0; nt < 8; nt++) {
            of[nt][0] *= a0; of[nt][1] *= a0; of[nt][2] *= a1; of[nt][3] *= a1;
        }
        __syncwarp();

        // O += P V  (A = own-warp P rows, B[n=d][k=key] read from key-major Vs)
#pragma unroll
        for (int ks = 0; ks < 8; ks++) {
            uint32_t af[4];
            af[0] = __float_as_uint(Ps[r0][ks*8 + qd]);
            af[1] = __float_as_uint(Ps[r0+8][ks*8 + qd]);
            af[2] = __float_as_uint(Ps[r0][ks*8 + qd + 4]);
            af[3] = __float_as_uint(Ps[r0+8][ks*8 + qd + 4]);
#pragma unroll
            for (int nt = 0; nt < 8; nt++) {
                uint32_t bf[2];
                int nr = nt * 8 + gr;
                bf[0] = __float_as_uint(Vs[ks*8 + qd][nr]);
                bf[1] = __float_as_uint(Vs[ks*8 + qd + 4][nr]);
                mma8(of[nt], af, bf);
            }
        }
    }

    const float il0 = 1.f / l0, il1 = 1.f / l1;
    float* Ob = O + (size_t)(b * SS + q0) * DD + h * HD;
#pragma unroll
    for (int nt = 0; nt < 8; nt++) {
        int cn = nt * 8 + 2 * qd;
        float2 o0 = { rtf(of[nt][0] * il0), rtf(of[nt][1] * il0) };
        float2 o1 = { rtf(of[nt][2] * il1), rtf(of[nt][3] * il1) };
        *(float2*)(Ob + (size_t)r0 * DD + cn) = o0;
        *(float2*)(Ob + (size_t)(r0 + 8) * DD + cn) = o1;
    }
}

// ================= unified tf32 GEMM (2-stage cp.async, R10 configuration) =================
// BM=128, BN=128, 8 warps 4(m)x2(n), warp tile 32x64. 2 CTAs/SM.
// MODE 0: projection (ROUND=1 rounds output). MODE 1: MoE fc1. MODE 2: MoE fc2.
template<int BN, int MODE, int ROUND = 0>
__global__ __launch_bounds__(256, 2) void gemm_tf32(
    const float* __restrict__ A, int lda,
    const float* __restrict__ Bg, int ldb,
    const float* __restrict__ bias,
    float* __restrict__ C, int ldc,
    int K, float scale)
{
    constexpr int NT  = BN / 16;
    constexpr int BF4 = BN * 32 / 4 / 256;
    extern __shared__ uint32_t smem_[];
    uint32_t (*As)[36] = (uint32_t(*)[36])smem_;
    uint32_t (*Bs)[36] = (uint32_t(*)[36])(smem_ + 2 * 128 * 36);

    const int tid = threadIdx.x;
    const int warp = tid >> 5, lane = tid & 31;
    const int gr = lane >> 2, qd = lane & 3;
    const int m_base = (warp >> 1) * 32;
    const int n_base = (warp & 1) * (BN / 2);
    const int bm = blockIdx.y * 128;
    const int bn = blockIdx.x * BN;
    const int zb = blockIdx.z;

    int count = 0, base = 0, rt = 0;
    const float* biasp = nullptr;
    const float* Bbase = nullptr;
    float* Cb = nullptr;

    if constexpr (MODE == 1) {
        count = g_counts[zb]; rt = bm; if (rt >= count) return; base = g_off[zb];
        Bbase = Bg + (size_t)zb * FF * DD + (size_t)bn * DD;
        biasp = bias + (size_t)zb * FF + bn;
    } else if constexpr (MODE == 2) {
        count = g_counts[zb]; rt = bm; if (rt >= count) return; base = g_off[zb];
        Bbase = Bg + (size_t)zb * DD * FF + (size_t)bn * FF;
        biasp = bias + (size_t)zb * DD + bn;
    } else {
        Bbase = Bg + (size_t)bn * ldb;
        biasp = bias ? bias + bn : nullptr;
        Cb = C + (size_t)bm * ldc + bn;
    }

    const int ldb_eff = (MODE == 1) ? DD : (MODE == 2) ? FF : ldb;

    const float* aptr[4];
    int arow[4], acol[4];
#pragma unroll
    for (int i = 0; i < 4; i++) {
        int f4 = i * 256 + tid;
        int r = f4 >> 3, c = (f4 & 7) * 4;
        arow[i] = r; acol[i] = c;
        if constexpr (MODE == 1) {
            int rr = rt + r; if (rr > count - 1) rr = count - 1;
            aptr[i] = A + (size_t)g_rowtok[base + rr] * DD + c;
        } else if constexpr (MODE == 2) {
            int rr = rt + r; if (rr > count - 1) rr = count - 1;
            aptr[i] = A + (size_t)(base + rr) * FF + c;
        } else {
            aptr[i] = A + (size_t)(bm + r) * lda + c;
        }
    }

    const float* bptr[BF4];
    int brow[BF4], bcol[BF4];
#pragma unroll
    for (int i = 0; i < BF4; i++) {
        int f4 = i * 256 + tid;
        int r = f4 >> 3, c = (f4 & 7) * 4;
        brow[i] = r; bcol[i] = c;
        bptr[i] = Bbase + (size_t)r * ldb_eff + c;
    }

    float cf[2][NT][4];
#pragma unroll
    for (int mt = 0; mt < 2; mt++)
#pragma unroll
        for (int nt = 0; nt < NT; nt++)
#pragma unroll
            for (int j = 0; j < 4; j++) cf[mt][nt][j] = 0.f;

    const int nIter = K >> 5;

#pragma unroll
    for (int i = 0; i < 4; i++)
        cp16(&As[arow[i]][acol[i]], aptr[i]);
#pragma unroll
    for (int i = 0; i < BF4; i++)
        cp16(&Bs[brow[i]][bcol[i]], bptr[i]);
    cp_commit();

    for (int it = 0; it < nIter; it++) {
        const int buf = it & 1;
        const int nbuf = buf ^ 1;
        if (it + 1 < nIter) {
            const int k0 = (it + 1) << 5;
#pragma unroll
            for (int i = 0; i < 4; i++)
                cp16(&As[nbuf * 128 + arow[i]][acol[i]], aptr[i] + k0);
#pragma unroll
            for (int i = 0; i < BF4; i++)
                cp16(&Bs[nbuf * BN + brow[i]][bcol[i]], bptr[i] + k0);
        }
        cp_commit();
        cp_wait1();
        __syncthreads();

        const uint32_t (*A_)[36] = (const uint32_t(*)[36])&As[buf * 128];
        const uint32_t (*B_)[36] = (const uint32_t(*)[36])&Bs[buf * BN];
#pragma unroll
        for (int kk = 0; kk < 32; kk += 8) {
            uint32_t af[2][4];
#pragma unroll
            for (int mt = 0; mt < 2; mt++) {
                int r0 = m_base + mt * 16 + gr;
                af[mt][0] = A_[r0][kk + qd];
                af[mt][1] = A_[r0 + 8][kk + qd];
                af[mt][2] = A_[r0][kk + qd + 4];
                af[mt][3] = A_[r0 + 8][kk + qd + 4];
            }
#pragma unroll
            for (int nt = 0; nt < NT; nt++) {
                uint32_t bf[2];
                int nr = n_base + nt * 8 + gr;
                bf[0] = B_[nr][kk + qd];
                bf[1] = B_[nr][kk + qd + 4];
#pragma unroll
                for (int mt = 0; mt < 2; mt++) mma8(cf[mt][nt], af[mt], bf);
            }
        }
        __syncthreads();
    }

#pragma unroll
    for (int mt = 0; mt < 2; mt++) {
#pragma unroll
        for (int half = 0; half < 2; half++) {
            int lr = m_base + mt * 16 + gr + half * 8;
#pragma unroll
            for (int nt = 0; nt < NT; nt++) {
                int cn = n_base + nt * 8 + qd * 2;
                float v0 = cf[mt][nt][half * 2 + 0];
                float v1 = cf[mt][nt][half * 2 + 1];
                if constexpr (MODE == 0) {
                    float b0 = biasp ? biasp[cn] : 0.f;
                    float b1 = biasp ? biasp[cn + 1] : 0.f;
                    float o0 = v0 * scale + b0, o1 = v1 * scale + b1;
                    if constexpr (ROUND) { o0 = rtf(o0); o1 = rtf(o1); }
                    float2 o = {o0, o1};
                    *(float2*)(Cb + (size_t)lr * ldc + cn) = o;
                } else if constexpr (MODE == 1) {
                    int grow = rt + lr;
                    if (grow < count) {
                        float* p = g_h + (size_t)(base + grow) * FF + bn + cn;
                        p[0] = rtf(fmaxf(v0 + biasp[cn], 0.f));
                        p[1] = rtf(fmaxf(v1 + biasp[cn + 1], 0.f));
                    }
                } else { // MODE == 2
                    int grow = rt + lr;
                    if (grow < count) {
                        float gate = g_rowgate[base + grow];
                        float* p = g_yb + (size_t)(base + grow) * DD + bn + cn;
                        p[0] = gate * (v0 + biasp[cn]);
                        p[1] = gate * (v1 + biasp[cn + 1]);
                    }
                }
            }
        }
    }
}

// ---------------- fused residual add + LayerNorm (+ optional rounded copy) ----------------
__global__ __launch_bounds__(256) void add_ln(
    const float* __restrict__ X, const float* __restrict__ Y,
    const float* __restrict__ gam, const float* __restrict__ bet,
    float* __restrict__ O, float* __restrict__ Or)
{
    __shared__ float red[256];
    const int t = blockIdx.x, tid = threadIdx.x;
    const float* x = X + (size_t)t * DD;
    const float* y = Y + (size_t)t * DD;
    float v[4]; float s = 0.f;
#pragma unroll
    for (int i = 0; i < 4; i++) { v[i] = x[tid + i * 256] + y[tid + i * 256]; s += v[i]; }
    red[tid] = s; __syncthreads();
    for (int st = 128; st > 0; st >>= 1) { if (tid < st) red[tid] += red[tid + st]; __syncthreads(); }
    const float mean = red[0] * (1.f / 1024.f);
    __syncthreads();
    float s2 = 0.f;
#pragma unroll
    for (int i = 0; i < 4; i++) { float d = v[i] - mean; s2 += d * d; }
    red[tid] = s2; __syncthreads();
    for (int st = 128; st > 0; st >>= 1) { if (tid < st) red[tid] += red[tid + st]; __syncthreads(); }
    const float inv = rsqrtf(red[0] * (1.f / 1024.f) + 1e-5f);
    float* o = O + (size_t)t * DD;
    float* orr = Or ? Or + (size_t)t * DD : nullptr;
#pragma unroll
    for (int i = 0; i < 4; i++) {
        int idx = tid + i * 256;
        float val = (v[i] - mean) * inv * gam[idx] + bet[idx];
        o[idx] = val;
        if (orr) orr[idx] = rtf(val);
    }
}

// ---------------- MoE router: noisy top-2 ----------------
__global__ void moe_init()
{
    if (threadIdx.x < EE) { g_counts[threadIdx.x] = 0; g_fill[threadIdx.x] = 0; }
}

__global__ __launch_bounds__(128) void router(
    const float* __restrict__ X,
    const float* __restrict__ wg, const float* __restrict__ bg,
    const float* __restrict__ wn, const float* __restrict__ bn,
    const float* __restrict__ eps)
{
    __shared__ float xs[1024];
    __shared__ float lg[32];
    const int t = blockIdx.x, tid = threadIdx.x;
    const float* x = X + (size_t)t * DD;
    for (int i = tid; i < 1024; i += 128) xs[i] = x[i];
    __syncthreads();
    const int warp = tid >> 5, lane = tid & 31;
    for (int dd = warp * 8; dd < warp * 8 + 8; dd++) {
        const float* w = (dd < 16) ? (wg + (size_t)dd * DD) : (wn + (size_t)(dd - 16) * DD);
        float s = 0.f;
        for (int i = lane; i < 1024; i += 32) s += xs[i] * w[i];
#pragma unroll
        for (int o = 16; o; o >>= 1) s += __shfl_xor_sync(0xffffffffu, s, o);
        if (lane == 0) lg[dd] = s;
    }
    __syncthreads();
    if (tid == 0) {
        float nv[16];
#pragma unroll
        for (int e = 0; e < 16; e++) {
            float gz = lg[e] + bg[e];
            float nz = lg[16 + e] + bn[e];
            float sp = (nz > 0.f) ? (nz + log1pf(expf(-nz))) : log1pf(expf(nz));
            nv[e] = gz + eps[(size_t)t * EE + e] * sp;
        }
        int i0 = 0; float v0 = nv[0];
        for (int e = 1; e < 16; e++) if (nv[e] > v0) { v0 = nv[e]; i0 = e; }
        int i1 = (i0 == 0) ? 1 : 0; float v1 = nv[i1];
        for (int e = 0; e < 16; e++) { if (e == i0) continue; if (nv[e] > v1) { v1 = nv[e]; i1 = e; } }
        float g0 = 1.f / (1.f + expf(v1 - v0));
        float g1 = 1.f - g0;
        g_eidx[2 * t] = i0; g_eidx[2 * t + 1] = i1;
        g_gval[2 * t] = g0; g_gval[2 * t + 1] = g1;
        atomicAdd(&g_counts[i0], 1);
        atomicAdd(&g_counts[i1], 1);
    }
}

__global__ void prefix16()
{
    if (threadIdx.x == 0) {
        int s = 0;
        for (int e = 0; e < EE; e++) { g_off[e] = s; s += g_counts[e]; }
    }
}

__global__ void scatter_moe()
{
    int i = blockIdx.x * blockDim.x + threadIdx.x;
    if (i >= NASSIGN) return;
    int e = g_eidx[i];
    int pos = atomicAdd(&g_fill[e], 1);
    int row = g_off[e] + pos;
    g_rowtok[row] = i >> 1;
    g_rowgate[row] = g_gval[i];
    g_arow[i] = row;
}

// ---------------- final: out = LN3(x2 + yb[r0] + yb[r1]) ----------------
__global__ __launch_bounds__(256) void moe_add_ln(
    const float* __restrict__ X,
    const float* __restrict__ gam, const float* __restrict__ bet,
    float* __restrict__ O)
{
    __shared__ float red[256];
    const int t = blockIdx.x, tid = threadIdx.x;
    const int r0 = g_arow[2 * t], r1 = g_arow[2 * t + 1];
    const float* x = X + (size_t)t * DD;
    const float* y0 = g_yb + (size_t)r0 * DD;
    const float* y1 = g_yb + (size_t)r1 * DD;
    float v[4]; float s = 0.f;
#pragma unroll
    for (int i = 0; i < 4; i++) {
        int idx = tid + i * 256;
        v[i] = x[idx] + y0[idx] + y1[idx];
        s += v[i];
    }
    red[tid] = s; __syncthreads();
    for (int st = 128; st > 0; st >>= 1) { if (tid < st) red[tid] += red[tid + st]; __syncthreads(); }
    const float mean = red[0] * (1.f / 1024.f);
    __syncthreads();
    float s2 = 0.f;
#pragma unroll
    for (int i = 0; i < 4; i++) { float d = v[i] - mean; s2 += d * d; }
    red[tid] = s2; __syncthreads();
    for (int st = 128; st > 0; st >>= 1) { if (tid < st) red[tid] += red[tid + st]; __syncthreads(); }
    const float inv = rsqrtf(red[0] * (1.f / 1024.f) + 1e-5f);
    float* o = O + (size_t)t * DD;
#pragma unroll
    for (int i = 0; i < 4; i++) {
        int idx = tid + i * 256;
        o[idx] = (v[i] - mean) * inv * gam[idx] + bet[idx];
    }
}

// ---------------- host launch ----------------
extern "C" void kernel_launch(void* const* d_in, const int* in_sizes, int n_in,
                              void* d_out, int out_size)
{
    const float* tgt      = (const float*)d_in[0];
    const float* memory   = (const float*)d_in[1];
    const float* noise    = (const float*)d_in[2];
    const float* sa_in_w  = (const float*)d_in[3];
    const float* sa_in_b  = (const float*)d_in[4];
    const float* sa_out_w = (const float*)d_in[5];
    const float* sa_out_b = (const float*)d_in[6];
    const float* ma_in_w  = (const float*)d_in[7];
    const float* ma_in_b  = (const float*)d_in[8];
    const float* ma_out_w = (const float*)d_in[9];
    const float* ma_out_b = (const float*)d_in[10];
    const float* wg       = (const float*)d_in[11];
    const float* bg       = (const float*)d_in[12];
    const float* wn       = (const float*)d_in[13];
    const float* bn       = (const float*)d_in[14];
    const float* w1       = (const float*)d_in[15];
    const float* b1       = (const float*)d_in[16];
    const float* w2       = (const float*)d_in[17];
    const float* b2       = (const float*)d_in[18];
    const float* ln1_g    = (const float*)d_in[19];
    const float* ln1_b    = (const float*)d_in[20];
    const float* ln2_g    = (const float*)d_in[21];
    const float* ln2_b    = (const float*)d_in[22];
    const float* ln3_g    = (const float*)d_in[23];
    const float* ln3_b    = (const float*)d_in[24];

    float *qkv, *kvx, *ctx, *proj, *x1, *x2, *x1r, *x2r, *hbuf;
    float *w1r, *w2r, *wpr, *tgtr, *memr;
    cudaGetSymbolAddress((void**)&qkv,    g_qkv);
    cudaGetSymbolAddress((void**)&kvx,    g_kvx);
    cudaGetSymbolAddress((void**)&ctx,    g_ctx);
    cudaGetSymbolAddress((void**)&proj,   g_proj);
    cudaGetSymbolAddress((void**)&x1,     g_x1);
    cudaGetSymbolAddress((void**)&x2,     g_x2);
    cudaGetSymbolAddress((void**)&x1r,    g_x1r);
    cudaGetSymbolAddress((void**)&x2r,    g_x2r);
    cudaGetSymbolAddress((void**)&hbuf,   g_h);
    cudaGetSymbolAddress((void**)&w1r,    g_w1r);
    cudaGetSymbolAddress((void**)&w2r,    g_w2r);
    cudaGetSymbolAddress((void**)&wpr,    g_wpr);
    cudaGetSymbolAddress((void**)&tgtr,   g_tgtr);
    cudaGetSymbolAddress((void**)&memr,   g_memr);

    // one-time stream/event creation (first call = uncaptured correctness run)
    static cudaStream_t s2 = []() {
        cudaStream_t s; cudaStreamCreateWithFlags(&s, cudaStreamNonBlocking); return s;
    }();
    static cudaEvent_t evA = []() {
        cudaEvent_t e; cudaEventCreateWithFlags(&e, cudaEventDisableTiming); return e;
    }();
    static cudaEvent_t evKV = []() {
        cudaEvent_t e; cudaEventCreateWithFlags(&e, cudaEventDisableTiming); return e;
    }();
    static cudaEvent_t evRB = []() {
        cudaEvent_t e; cudaEventCreateWithFlags(&e, cudaEventDisableTiming); return e;
    }();

    const float scale = 0.125f;  // 1/sqrt(64)
    const int M1 = DD * DD;

    const int smem128 = 2 * (128 + 128) * 36 * 4;   // 73728
    const int smemFA  = (64 + 64 + 128) * 68 * 4;   // 69632
    cudaFuncSetAttribute(gemm_tf32<128,0,0>, cudaFuncAttributeMaxDynamicSharedMemorySize, smem128);
    cudaFuncSetAttribute(gemm_tf32<128,0,1>, cudaFuncAttributeMaxDynamicSharedMemorySize, smem128);
    cudaFuncSetAttribute(gemm_tf32<128,1,0>, cudaFuncAttributeMaxDynamicSharedMemorySize, smem128);
    cudaFuncSetAttribute(gemm_tf32<128,2,0>, cudaFuncAttributeMaxDynamicSharedMemorySize, smem128);
    cudaFuncSetAttribute(flash_attn,         cudaFuncAttributeMaxDynamicSharedMemorySize, smemFA);

    // ===== round attention weights + inputs (critical path) =====
    roundA<<<dim3(1024, 6), 256>>>(
        (const float4*)sa_in_w,  (float4*)(wpr),        3*M1/4,
        (const float4*)sa_out_w, (float4*)(wpr + 3*M1), M1/4,
        (const float4*)ma_in_w,  (float4*)(wpr + 4*M1), 3*M1/4,
        (const float4*)ma_out_w, (float4*)(wpr + 7*M1), M1/4,
        (const float4*)tgt,      (float4*)tgtr,         NTOK*DD/4,
        (const float4*)memory,   (float4*)memr,         NTOK*DD/4);
    cudaEventRecord(evA, 0);

    // ===== side stream: cross-attn KV projection + MoE weight rounding =====
    cudaStreamWaitEvent(s2, evA, 0);
    gemm_tf32<128,0,1><<<dim3(2*DD/128, NTOK/128), 256, smem128, s2>>>(
        memr, DD, wpr + 5*M1, DD, ma_in_b + DD, kvx, 2*DD, DD, 1.f);
    cudaEventRecord(evKV, s2);
    roundB<<<dim3(4096, 2), 256, 0, s2>>>(
        (const float4*)w1, (float4*)w1r, (int)((size_t)EE*FF*DD/4),
        (const float4*)w2, (float4*)w2r, (int)((size_t)EE*DD*FF/4));
    cudaEventRecord(evRB, s2);

    // ===== Self-attention (main stream) =====
    gemm_tf32<128,0,1><<<dim3(3*DD/128, NTOK/128), 256, smem128>>>(tgtr, DD, wpr, DD, sa_in_b, qkv, 3*DD, DD, 1.f);
    flash_attn<<<dim3(SS/128, BB*HH), 256, smemFA>>>(qkv, 3*DD, qkv + DD, qkv + 2*DD, 3*DD, ctx, scale);
    gemm_tf32<128,0,0><<<dim3(DD/128, NTOK/128), 256, smem128>>>(ctx, DD, wpr + 3*M1, DD, sa_out_b, proj, DD, DD, 1.f);
    add_ln<<<NTOK, 256>>>(tgt, proj, ln1_g, ln1_b, x1, x1r);

    // ===== Cross-attention =====
    gemm_tf32<128,0,1><<<dim3(DD/128, NTOK/128), 256, smem128>>>(x1r, DD, wpr + 4*M1, DD, ma_in_b, qkv, DD, DD, 1.f);
    cudaStreamWaitEvent(0, evKV, 0);
    flash_attn<<<dim3(SS/128, BB*HH), 256, smemFA>>>(qkv, DD, kvx, kvx + DD, 2*DD, ctx, scale);
    gemm_tf32<128,0,0><<<dim3(DD/128, NTOK/128), 256, smem128>>>(ctx, DD, wpr + 7*M1, DD, ma_out_b, proj, DD, DD, 1.f);
    add_ln<<<NTOK, 256>>>(x1, proj, ln2_g, ln2_b, x2, x2r);

    // ===== MoE (sparse top-2) =====
    moe_init<<<1, 32>>>();
    router<<<NTOK, 128>>>(x2, wg, bg, wn, bn, noise);
    prefix16<<<1, 32>>>();
    scatter_moe<<<NASSIGN/256, 256>>>();
    cudaStreamWaitEvent(0, evRB, 0);
    gemm_tf32<128,1,0><<<dim3(FF/128, NASSIGN/128, EE), 256, smem128>>>(x2r, 0, w1r, DD, b1, nullptr, 0, DD, 1.f);
    gemm_tf32<128,2,0><<<dim3(DD/128, NASSIGN/128, EE), 256, smem128>>>(hbuf, 0, w2r, FF, b2, nullptr, 0, FF, 1.f);
    moe_add_ln<<<NTOK, 256>>>(x2, ln3_g, ln3_b, (float*)d_out);
}

// round 15
// speedup vs baseline: 1.0270x; 1.0270x over previous
#include <cuda_runtime.h>
#include <math.h>
#include <stdint.h>

// Problem dims
#define BB 4
#define SS 1024
#define DD 1024
#define HH 16
#define HD 64
#define EE 16
#define FF 2048
#define NTOK (BB*SS)        // 4096
#define NASSIGN (NTOK*2)    // 8192

// ---------------- scratch (static device memory; no allocations) ----------------
__device__ __align__(256) float g_qkv[NTOK*3*DD];
__device__ __align__(256) float g_kvx[NTOK*2*DD];    // cross-attn K|V
__device__ __align__(256) float g_ctx[NTOK*DD];
__device__ __align__(256) float g_proj[NTOK*DD];
__device__ __align__(256) float g_x1[NTOK*DD];
__device__ __align__(256) float g_x2[NTOK*DD];
__device__ __align__(256) float g_x1r[NTOK*DD];
__device__ __align__(256) float g_x2r[NTOK*DD];
__device__ __align__(256) float g_h[(size_t)NASSIGN*FF];
__device__ __align__(256) float g_yb[(size_t)NASSIGN*DD];
// rounded weight / input copies
__device__ __align__(256) float g_w1r[(size_t)EE*FF*DD];
__device__ __align__(256) float g_w2r[(size_t)EE*DD*FF];
__device__ __align__(256) float g_wpr[8*DD*DD];
__device__ __align__(256) float g_tgtr[NTOK*DD];
__device__ __align__(256) float g_memr[NTOK*DD];
__device__ int   g_eidx[NASSIGN];
__device__ float g_gval[NASSIGN];
__device__ int   g_counts[EE];
__device__ int   g_off[EE];
__device__ int   g_fill[EE];
__device__ int   g_rowtok[NASSIGN];
__device__ float g_rowgate[NASSIGN];
__device__ int   g_arow[NASSIGN];

// ---------------- helpers ----------------
__device__ __forceinline__ float rtf(float f) {
    uint32_t u;
    asm("cvt.rna.tf32.f32 %0, %1;" : "=r"(u) : "f"(f));
    return __uint_as_float(u);
}

__device__ __forceinline__ void mma8(float* c, const uint32_t* a, const uint32_t* b) {
    asm volatile(
        "mma.sync.aligned.m16n8k8.row.col.f32.tf32.tf32.f32 "
        "{%0,%1,%2,%3}, {%4,%5,%6,%7}, {%8,%9}, {%0,%1,%2,%3};"
        : "+f"(c[0]), "+f"(c[1]), "+f"(c[2]), "+f"(c[3])
        : "r"(a[0]), "r"(a[1]), "r"(a[2]), "r"(a[3]), "r"(b[0]), "r"(b[1]));
}

__device__ __forceinline__ void cp16(void* smem_dst, const void* gmem_src) {
    uint32_t d = (uint32_t)__cvta_generic_to_shared(smem_dst);
    asm volatile("cp.async.cg.shared.global [%0], [%1], 16;" :: "r"(d), "l"(gmem_src) : "memory");
}
__device__ __forceinline__ void cp_commit() {
    asm volatile("cp.async.commit_group;" ::: "memory");
}
__device__ __forceinline__ void cp_wait1() {
    asm volatile("cp.async.wait_group 1;" ::: "memory");
}
__device__ __forceinline__ void cp_wait0() {
    asm volatile("cp.async.wait_group 0;" ::: "memory");
}

// ---------------- tf32 RN rounding: attention weights + inputs (6 segments) ----------------
__global__ __launch_bounds__(256) void roundA(
    const float4* s0, float4* d0, int n0,
    const float4* s1, float4* d1, int n1,
    const float4* s2, float4* d2, int n2,
    const float4* s3, float4* d3, int n3,
    const float4* s4, float4* d4, int n4,
    const float4* s5, float4* d5, int n5)
{
    const float4* src; float4* dst; int n4c;
    switch (blockIdx.y) {
        case 0: src = s0; dst = d0; n4c = n0; break;
        case 1: src = s1; dst = d1; n4c = n1; break;
        case 2: src = s2; dst = d2; n4c = n2; break;
        case 3: src = s3; dst = d3; n4c = n3; break;
        case 4: src = s4; dst = d4; n4c = n4; break;
        default: src = s5; dst = d5; n4c = n5; break;
    }
    for (int i = blockIdx.x * blockDim.x + threadIdx.x; i < n4c; i += gridDim.x * blockDim.x) {
        float4 v = src[i];
        v.x = rtf(v.x); v.y = rtf(v.y); v.z = rtf(v.z); v.w = rtf(v.w);
        dst[i] = v;
    }
}

// ---------------- tf32 RN rounding: MoE weights (2 segments) ----------------
__global__ __launch_bounds__(256) void roundB(
    const float4* s0, float4* d0, int n0,
    const float4* s1, float4* d1, int n1)
{
    const float4* src = blockIdx.y ? s1 : s0;
    float4* dst = blockIdx.y ? d1 : d0;
    int n4c = blockIdx.y ? n1 : n0;
    for (int i = blockIdx.x * blockDim.x + threadIdx.x; i < n4c; i += gridDim.x * blockDim.x) {
        float4 v = src[i];
        v.x = rtf(v.x); v.y = rtf(v.y); v.z = rtf(v.z); v.w = rtf(v.w);
        dst[i] = v;
    }
}

// ================= fused flash attention (tf32 MMA, cp.async double-buffered K/V) =================
// One barrier per iteration: wait0 -> sync -> prefetch kt+1 -> compute kt.
// K and V both key-major in smem.
__global__ __launch_bounds__(256) void flash_attn(
    const float* __restrict__ Q, int ldq,
    const float* __restrict__ Kp, const float* __restrict__ Vp, int ldkv,
    float* __restrict__ O, float scale)
{
    extern __shared__ float fsm[];
    float (*Ks)[68] = (float(*)[68])fsm;                   // [2*64][68] key-major
    float (*Vs)[68] = (float(*)[68])(fsm + 2*64*68);       // [2*64][68] key-major
    float (*Ps)[68] = (float(*)[68])(fsm + 4*64*68);       // [128][68]

    const int tid = threadIdx.x, warp = tid >> 5, lane = tid & 31;
    const int gr = lane >> 2, qd = lane & 3;
    const int z = blockIdx.y, b = z >> 4, h = z & 15;
    const int q0 = blockIdx.x * 128;
    const float* Qb = Q  + (size_t)(b * SS + q0) * ldq  + h * HD;
    const float* Kb = Kp + (size_t)(b * SS) * ldkv + h * HD;
    const float* Vb = Vp + (size_t)(b * SS) * ldkv + h * HD;

    // per-thread K/V load slots: 4 chunks over 64x64 tile
    int lrow[4], lcol[4];
#pragma unroll
    for (int i = 0; i < 4; i++) {
        int f4 = i * 256 + tid;
        lrow[i] = f4 >> 4;
        lcol[i] = (f4 & 15) * 4;
    }

    // stage Q tile 128x64 into Ps, lift fragments
#pragma unroll
    for (int i = 0; i < 8; i++) {
        int f4 = i * 256 + tid;
        int r = f4 >> 4, c = (f4 & 15) * 4;
        *(float4*)&Ps[r][c] = *(const float4*)(Qb + (size_t)r * ldq + c);
    }
    __syncthreads();
    uint32_t qf[8][4];
    const int r0 = warp * 16 + gr;
#pragma unroll
    for (int ks = 0; ks < 8; ks++) {
        qf[ks][0] = __float_as_uint(Ps[r0][ks*8 + qd]);
        qf[ks][1] = __float_as_uint(Ps[r0+8][ks*8 + qd]);
        qf[ks][2] = __float_as_uint(Ps[r0][ks*8 + qd + 4]);
        qf[ks][3] = __float_as_uint(Ps[r0+8][ks*8 + qd + 4]);
    }
    __syncthreads();   // Q fragment reads done before P writes reuse Ps

    float of[8][4];
#pragma unroll
    for (int nt = 0; nt < 8; nt++) { of[nt][0]=of[nt][1]=of[nt][2]=of[nt][3]=0.f; }
    float m0 = -1e30f, m1 = -1e30f, l0 = 0.f, l1 = 0.f;

    // prologue: kt=0 into buf 0
#pragma unroll
    for (int i = 0; i < 4; i++) {
        cp16(&Ks[lrow[i]][lcol[i]], Kb + (size_t)lrow[i] * ldkv + lcol[i]);
        cp16(&Vs[lrow[i]][lcol[i]], Vb + (size_t)lrow[i] * ldkv + lcol[i]);
    }
    cp_commit();

    for (int kt = 0; kt < SS / 64; kt++) {
        const int buf = (kt & 1) * 64;
        cp_wait0();
        __syncthreads();   // kt data visible to all; compute kt-1 reads done

        if (kt + 1 < SS / 64) {
            const int nbuf = ((kt + 1) & 1) * 64;
            const size_t kbase = (size_t)((kt + 1) * 64);
#pragma unroll
            for (int i = 0; i < 4; i++) {
                cp16(&Ks[nbuf + lrow[i]][lcol[i]], Kb + (kbase + lrow[i]) * ldkv + lcol[i]);
                cp16(&Vs[nbuf + lrow[i]][lcol[i]], Vb + (kbase + lrow[i]) * ldkv + lcol[i]);
            }
        }
        cp_commit();

        float sf[8][4];
#pragma unroll
        for (int nt = 0; nt < 8; nt++) { sf[nt][0]=sf[nt][1]=sf[nt][2]=sf[nt][3]=0.f; }
#pragma unroll
        for (int ks = 0; ks < 8; ks++) {
#pragma unroll
            for (int nt = 0; nt < 8; nt++) {
                uint32_t bf[2];
                int nr = nt * 8 + gr;
                bf[0] = __float_as_uint(Ks[buf + nr][ks*8 + qd]);
                bf[1] = __float_as_uint(Ks[buf + nr][ks*8 + qd + 4]);
                mma8(sf[nt], qf[ks], bf);
            }
        }

        float tm0 = -1e30f, tm1 = -1e30f;
#pragma unroll
        for (int nt = 0; nt < 8; nt++) {
            sf[nt][0] *= scale; sf[nt][1] *= scale; sf[nt][2] *= scale; sf[nt][3] *= scale;
            tm0 = fmaxf(tm0, fmaxf(sf[nt][0], sf[nt][1]));
            tm1 = fmaxf(tm1, fmaxf(sf[nt][2], sf[nt][3]));
        }
        tm0 = fmaxf(tm0, __shfl_xor_sync(~0u, tm0, 1));
        tm0 = fmaxf(tm0, __shfl_xor_sync(~0u, tm0, 2));
        tm1 = fmaxf(tm1, __shfl_xor_sync(~0u, tm1, 1));
        tm1 = fmaxf(tm1, __shfl_xor_sync(~0u, tm1, 2));
        const float mn0 = fmaxf(m0, tm0), mn1 = fmaxf(m1, tm1);
        const float a0 = __expf(m0 - mn0), a1 = __expf(m1 - mn1);
        float ts0 = 0.f, ts1 = 0.f;
#pragma unroll
        for (int nt = 0; nt < 8; nt++) {
            float p0 = __expf(sf[nt][0] - mn0), p1 = __expf(sf[nt][1] - mn0);
            float p2 = __expf(sf[nt][2] - mn1), p3 = __expf(sf[nt][3] - mn1);
            ts0 += p0 + p1; ts1 += p2 + p3;
            int cn = nt * 8 + 2 * qd;
            Ps[r0][cn] = rtf(p0);   Ps[r0][cn+1] = rtf(p1);
            Ps[r0+8][cn] = rtf(p2); Ps[r0+8][cn+1] = rtf(p3);
        }
        ts0 += __shfl_xor_sync(~0u, ts0, 1); ts0 += __shfl_xor_sync(~0u, ts0, 2);
        ts1 += __shfl_xor_sync(~0u, ts1, 1); ts1 += __shfl_xor_sync(~0u, ts1, 2);
        l0 = a0 * l0 + ts0; l1 = a1 * l1 + ts1;
        m0 = mn0; m1 = mn1;
#pragma unroll
        for (int nt = 0; nt < 8; nt++) {
            of[nt][0] *= a0; of[nt][1] *= a0; of[nt][2] *= a1; of[nt][3] *= a1;
        }
        __syncwarp();

        // O += P V   (B[n=d][k=key] from key-major Vs)
#pragma unroll
        for (int ks = 0; ks < 8; ks++) {
            uint32_t af[4];
            af[0] = __float_as_uint(Ps[r0][ks*8 + qd]);
            af[1] = __float_as_uint(Ps[r0+8][ks*8 + qd]);
            af[2] = __float_as_uint(Ps[r0][ks*8 + qd + 4]);
            af[3] = __float_as_uint(Ps[r0+8][ks*8 + qd + 4]);
#pragma unroll
            for (int nt = 0; nt < 8; nt++) {
                uint32_t bf[2];
                int nr = nt * 8 + gr;
                bf[0] = __float_as_uint(Vs[buf + ks*8 + qd][nr]);
                bf[1] = __float_as_uint(Vs[buf + ks*8 + qd + 4][nr]);
                mma8(of[nt], af, bf);
            }
        }
    }

    const float il0 = 1.f / l0, il1 = 1.f / l1;
    float* Ob = O + (size_t)(b * SS + q0) * DD + h * HD;
#pragma unroll
    for (int nt = 0; nt < 8; nt++) {
        int cn = nt * 8 + 2 * qd;
        float2 o0 = { rtf(of[nt][0] * il0), rtf(of[nt][1] * il0) };
        float2 o1 = { rtf(of[nt][2] * il1), rtf(of[nt][3] * il1) };
        *(float2*)(Ob + (size_t)r0 * DD + cn) = o0;
        *(float2*)(Ob + (size_t)(r0 + 8) * DD + cn) = o1;
    }
}

// ================= unified tf32 GEMM (2-stage cp.async, R10/R12 configuration) =================
template<int BN, int MODE, int ROUND = 0>
__global__ __launch_bounds__(256, 2) void gemm_tf32(
    const float* __restrict__ A, int lda,
    const float* __restrict__ Bg, int ldb,
    const float* __restrict__ bias,
    float* __restrict__ C, int ldc,
    int K, float scale)
{
    constexpr int NT  = BN / 16;
    constexpr int BF4 = BN * 32 / 4 / 256;
    extern __shared__ uint32_t smem_[];
    uint32_t (*As)[36] = (uint32_t(*)[36])smem_;
    uint32_t (*Bs)[36] = (uint32_t(*)[36])(smem_ + 2 * 128 * 36);

    const int tid = threadIdx.x;
    const int warp = tid >> 5, lane = tid & 31;
    const int gr = lane >> 2, qd = lane & 3;
    const int m_base = (warp >> 1) * 32;
    const int n_base = (warp & 1) * (BN / 2);
    const int bm = blockIdx.y * 128;
    const int bn = blockIdx.x * BN;
    const int zb = blockIdx.z;

    int count = 0, base = 0, rt = 0;
    const float* biasp = nullptr;
    const float* Bbase = nullptr;
    float* Cb = nullptr;

    if constexpr (MODE == 1) {
        count = g_counts[zb]; rt = bm; if (rt >= count) return; base = g_off[zb];
        Bbase = Bg + (size_t)zb * FF * DD + (size_t)bn * DD;
        biasp = bias + (size_t)zb * FF + bn;
    } else if constexpr (MODE == 2) {
        count = g_counts[zb]; rt = bm; if (rt >= count) return; base = g_off[zb];
        Bbase = Bg + (size_t)zb * DD * FF + (size_t)bn * FF;
        biasp = bias + (size_t)zb * DD + bn;
    } else {
        Bbase = Bg + (size_t)bn * ldb;
        biasp = bias ? bias + bn : nullptr;
        Cb = C + (size_t)bm * ldc + bn;
    }

    const int ldb_eff = (MODE == 1) ? DD : (MODE == 2) ? FF : ldb;

    const float* aptr[4];
    int arow[4], acol[4];
#pragma unroll
    for (int i = 0; i < 4; i++) {
        int f4 = i * 256 + tid;
        int r = f4 >> 3, c = (f4 & 7) * 4;
        arow[i] = r; acol[i] = c;
        if constexpr (MODE == 1) {
            int rr = rt + r; if (rr > count - 1) rr = count - 1;
            aptr[i] = A + (size_t)g_rowtok[base + rr] * DD + c;
        } else if constexpr (MODE == 2) {
            int rr = rt + r; if (rr > count - 1) rr = count - 1;
            aptr[i] = A + (size_t)(base + rr) * FF + c;
        } else {
            aptr[i] = A + (size_t)(bm + r) * lda + c;
        }
    }

    const float* bptr[BF4];
    int brow[BF4], bcol[BF4];
#pragma unroll
    for (int i = 0; i < BF4; i++) {
        int f4 = i * 256 + tid;
        int r = f4 >> 3, c = (f4 & 7) * 4;
        brow[i] = r; bcol[i] = c;
        bptr[i] = Bbase + (size_t)r * ldb_eff + c;
    }

    float cf[2][NT][4];
#pragma unroll
    for (int mt = 0; mt < 2; mt++)
#pragma unroll
        for (int nt = 0; nt < NT; nt++)
#pragma unroll
            for (int j = 0; j < 4; j++) cf[mt][nt][j] = 0.f;

    const int nIter = K >> 5;

#pragma unroll
    for (int i = 0; i < 4; i++)
        cp16(&As[arow[i]][acol[i]], aptr[i]);
#pragma unroll
    for (int i = 0; i < BF4; i++)
        cp16(&Bs[brow[i]][bcol[i]], bptr[i]);
    cp_commit();

    for (int it = 0; it < nIter; it++) {
        const int buf = it & 1;
        const int nbuf = buf ^ 1;
        if (it + 1 < nIter) {
            const int k0 = (it + 1) << 5;
#pragma unroll
            for (int i = 0; i < 4; i++)
                cp16(&As[nbuf * 128 + arow[i]][acol[i]], aptr[i] + k0);
#pragma unroll
            for (int i = 0; i < BF4; i++)
                cp16(&Bs[nbuf * BN + brow[i]][bcol[i]], bptr[i] + k0);
        }
        cp_commit();
        cp_wait1();
        __syncthreads();

        const uint32_t (*A_)[36] = (const uint32_t(*)[36])&As[buf * 128];
        const uint32_t (*B_)[36] = (const uint32_t(*)[36])&Bs[buf * BN];
#pragma unroll
        for (int kk = 0; kk < 32; kk += 8) {
            uint32_t af[2][4];
#pragma unroll
            for (int mt = 0; mt < 2; mt++) {
                int r0 = m_base + mt * 16 + gr;
                af[mt][0] = A_[r0][kk + qd];
                af[mt][1] = A_[r0 + 8][kk + qd];
                af[mt][2] = A_[r0][kk + qd + 4];
                af[mt][3] = A_[r0 + 8][kk + qd + 4];
            }
#pragma unroll
            for (int nt = 0; nt < NT; nt++) {
                uint32_t bf[2];
                int nr = n_base + nt * 8 + gr;
                bf[0] = B_[nr][kk + qd];
                bf[1] = B_[nr][kk + qd + 4];
#pragma unroll
                for (int mt = 0; mt < 2; mt++) mma8(cf[mt][nt], af[mt], bf);
            }
        }
        __syncthreads();
    }

#pragma unroll
    for (int mt = 0; mt < 2; mt++) {
#pragma unroll
        for (int half = 0; half < 2; half++) {
            int lr = m_base + mt * 16 + gr + half * 8;
#pragma unroll
            for (int nt = 0; nt < NT; nt++) {
                int cn = n_base + nt * 8 + qd * 2;
                float v0 = cf[mt][nt][half * 2 + 0];
                float v1 = cf[mt][nt][half * 2 + 1];
                if constexpr (MODE == 0) {
                    float b0 = biasp ? biasp[cn] : 0.f;
                    float b1 = biasp ? biasp[cn + 1] : 0.f;
                    float o0 = v0 * scale + b0, o1 = v1 * scale + b1;
                    if constexpr (ROUND) { o0 = rtf(o0); o1 = rtf(o1); }
                    float2 o = {o0, o1};
                    *(float2*)(Cb + (size_t)lr * ldc + cn) = o;
                } else if constexpr (MODE == 1) {
                    int grow = rt + lr;
                    if (grow < count) {
                        float* p = g_h + (size_t)(base + grow) * FF + bn + cn;
                        p[0] = rtf(fmaxf(v0 + biasp[cn], 0.f));
                        p[1] = rtf(fmaxf(v1 + biasp[cn + 1], 0.f));
                    }
                } else { // MODE == 2
                    int grow = rt + lr;
                    if (grow < count) {
                        float gate = g_rowgate[base + grow];
                        float* p = g_yb + (size_t)(base + grow) * DD + bn + cn;
                        p[0] = gate * (v0 + biasp[cn]);
                        p[1] = gate * (v1 + biasp[cn + 1]);
                    }
                }
            }
        }
    }
}

// ---------------- fused residual add + LayerNorm (+ optional rounded copy) ----------------
__global__ __launch_bounds__(256) void add_ln(
    const float* __restrict__ X, const float* __restrict__ Y,
    const float* __restrict__ gam, const float* __restrict__ bet,
    float* __restrict__ O, float* __restrict__ Or)
{
    __shared__ float red[256];
    const int t = blockIdx.x, tid = threadIdx.x;
    const float* x = X + (size_t)t * DD;
    const float* y = Y + (size_t)t * DD;
    float v[4]; float s = 0.f;
#pragma unroll
    for (int i = 0; i < 4; i++) { v[i] = x[tid + i * 256] + y[tid + i * 256]; s += v[i]; }
    red[tid] = s; __syncthreads();
    for (int st = 128; st > 0; st >>= 1) { if (tid < st) red[tid] += red[tid + st]; __syncthreads(); }
    const float mean = red[0] * (1.f / 1024.f);
    __syncthreads();
    float s2 = 0.f;
#pragma unroll
    for (int i = 0; i < 4; i++) { float d = v[i] - mean; s2 += d * d; }
    red[tid] = s2; __syncthreads();
    for (int st = 128; st > 0; st >>= 1) { if (tid < st) red[tid] += red[tid + st]; __syncthreads(); }
    const float inv = rsqrtf(red[0] * (1.f / 1024.f) + 1e-5f);
    float* o = O + (size_t)t * DD;
    float* orr = Or ? Or + (size_t)t * DD : nullptr;
#pragma unroll
    for (int i = 0; i < 4; i++) {
        int idx = tid + i * 256;
        float val = (v[i] - mean) * inv * gam[idx] + bet[idx];
        o[idx] = val;
        if (orr) orr[idx] = rtf(val);
    }
}

// ---------------- MoE router: noisy top-2 ----------------
__global__ void moe_init()
{
    if (threadIdx.x < EE) { g_counts[threadIdx.x] = 0; g_fill[threadIdx.x] = 0; }
}

__global__ __launch_bounds__(128) void router(
    const float* __restrict__ X,
    const float* __restrict__ wg, const float* __restrict__ bg,
    const float* __restrict__ wn, const float* __restrict__ bn,
    const float* __restrict__ eps)
{
    __shared__ float xs[1024];
    __shared__ float lg[32];
    const int t = blockIdx.x, tid = threadIdx.x;
    const float* x = X + (size_t)t * DD;
    for (int i = tid; i < 1024; i += 128) xs[i] = x[i];
    __syncthreads();
    const int warp = tid >> 5, lane = tid & 31;
    for (int dd = warp * 8; dd < warp * 8 + 8; dd++) {
        const float* w = (dd < 16) ? (wg + (size_t)dd * DD) : (wn + (size_t)(dd - 16) * DD);
        float s = 0.f;
        for (int i = lane; i < 1024; i += 32) s += xs[i] * w[i];
#pragma unroll
        for (int o = 16; o; o >>= 1) s += __shfl_xor_sync(0xffffffffu, s, o);
        if (lane == 0) lg[dd] = s;
    }
    __syncthreads();
    if (tid == 0) {
        float nv[16];
#pragma unroll
        for (int e = 0; e < 16; e++) {
            float gz = lg[e] + bg[e];
            float nz = lg[16 + e] + bn[e];
            float sp = (nz > 0.f) ? (nz + log1pf(expf(-nz))) : log1pf(expf(nz));
            nv[e] = gz + eps[(size_t)t * EE + e] * sp;
        }
        int i0 = 0; float v0 = nv[0];
        for (int e = 1; e < 16; e++) if (nv[e] > v0) { v0 = nv[e]; i0 = e; }
        int i1 = (i0 == 0) ? 1 : 0; float v1 = nv[i1];
        for (int e = 0; e < 16; e++) { if (e == i0) continue; if (nv[e] > v1) { v1 = nv[e]; i1 = e; } }
        float g0 = 1.f / (1.f + expf(v1 - v0));
        float g1 = 1.f - g0;
        g_eidx[2 * t] = i0; g_eidx[2 * t + 1] = i1;
        g_gval[2 * t] = g0; g_gval[2 * t + 1] = g1;
        atomicAdd(&g_counts[i0], 1);
        atomicAdd(&g_counts[i1], 1);
    }
}

// ---------------- fused prefix + scatter (one block) ----------------
__global__ __launch_bounds__(256) void prefix_scatter()
{
    const int tid = threadIdx.x;
    if (tid == 0) {
        int s = 0;
        for (int e = 0; e < EE; e++) { g_off[e] = s; s += g_counts[e]; }
    }
    __syncthreads();
    for (int i = tid; i < NASSIGN; i += 256) {
        int e = g_eidx[i];
        int pos = atomicAdd(&g_fill[e], 1);
        int row = g_off[e] + pos;
        g_rowtok[row] = i >> 1;
        g_rowgate[row] = g_gval[i];
        g_arow[i] = row;
    }
}

// ---------------- final: out = LN3(x2 + yb[r0] + yb[r1]) ----------------
__global__ __launch_bounds__(256) void moe_add_ln(
    const float* __restrict__ X,
    const float* __restrict__ gam, const float* __restrict__ bet,
    float* __restrict__ O)
{
    __shared__ float red[256];
    const int t = blockIdx.x, tid = threadIdx.x;
    const int r0 = g_arow[2 * t], r1 = g_arow[2 * t + 1];
    const float* x = X + (size_t)t * DD;
    const float* y0 = g_yb + (size_t)r0 * DD;
    const float* y1 = g_yb + (size_t)r1 * DD;
    float v[4]; float s = 0.f;
#pragma unroll
    for (int i = 0; i < 4; i++) {
        int idx = tid + i * 256;
        v[i] = x[idx] + y0[idx] + y1[idx];
        s += v[i];
    }
    red[tid] = s; __syncthreads();
    for (int st = 128; st > 0; st >>= 1) { if (tid < st) red[tid] += red[tid + st]; __syncthreads(); }
    const float mean = red[0] * (1.f / 1024.f);
    __syncthreads();
    float s2 = 0.f;
#pragma unroll
    for (int i = 0; i < 4; i++) { float d = v[i] - mean; s2 += d * d; }
    red[tid] = s2; __syncthreads();
    for (int st = 128; st > 0; st >>= 1) { if (tid < st) red[tid] += red[tid + st]; __syncthreads(); }
    const float inv = rsqrtf(red[0] * (1.f / 1024.f) + 1e-5f);
    float* o = O + (size_t)t * DD;
#pragma unroll
    for (int i = 0; i < 4; i++) {
        int idx = tid + i * 256;
        o[idx] = (v[i] - mean) * inv * gam[idx] + bet[idx];
    }
}

// ---------------- host launch ----------------
extern "C" void kernel_launch(void* const* d_in, const int* in_sizes, int n_in,
                              void* d_out, int out_size)
{
    const float* tgt      = (const float*)d_in[0];
    const float* memory   = (const float*)d_in[1];
    const float* noise    = (const float*)d_in[2];
    const float* sa_in_w  = (const float*)d_in[3];
    const float* sa_in_b  = (const float*)d_in[4];
    const float* sa_out_w = (const float*)d_in[5];
    const float* sa_out_b = (const float*)d_in[6];
    const float* ma_in_w  = (const float*)d_in[7];
    const float* ma_in_b  = (const float*)d_in[8];
    const float* ma_out_w = (const float*)d_in[9];
    const float* ma_out_b = (const float*)d_in[10];
    const float* wg       = (const float*)d_in[11];
    const float* bg       = (const float*)d_in[12];
    const float* wn       = (const float*)d_in[13];
    const float* bn       = (const float*)d_in[14];
    const float* w1       = (const float*)d_in[15];
    const float* b1       = (const float*)d_in[16];
    const float* w2       = (const float*)d_in[17];
    const float* b2       = (const float*)d_in[18];
    const float* ln1_g    = (const float*)d_in[19];
    const float* ln1_b    = (const float*)d_in[20];
    const float* ln2_g    = (const float*)d_in[21];
    const float* ln2_b    = (const float*)d_in[22];
    const float* ln3_g    = (const float*)d_in[23];
    const float* ln3_b    = (const float*)d_in[24];

    float *qkv, *kvx, *ctx, *proj, *x1, *x2, *x1r, *x2r, *hbuf;
    float *w1r, *w2r, *wpr, *tgtr, *memr;
    cudaGetSymbolAddress((void**)&qkv,    g_qkv);
    cudaGetSymbolAddress((void**)&kvx,    g_kvx);
    cudaGetSymbolAddress((void**)&ctx,    g_ctx);
    cudaGetSymbolAddress((void**)&proj,   g_proj);
    cudaGetSymbolAddress((void**)&x1,     g_x1);
    cudaGetSymbolAddress((void**)&x2,     g_x2);
    cudaGetSymbolAddress((void**)&x1r,    g_x1r);
    cudaGetSymbolAddress((void**)&x2r,    g_x2r);
    cudaGetSymbolAddress((void**)&hbuf,   g_h);
    cudaGetSymbolAddress((void**)&w1r,    g_w1r);
    cudaGetSymbolAddress((void**)&w2r,    g_w2r);
    cudaGetSymbolAddress((void**)&wpr,    g_wpr);
    cudaGetSymbolAddress((void**)&tgtr,   g_tgtr);
    cudaGetSymbolAddress((void**)&memr,   g_memr);

    // one-time stream/event creation (first call = uncaptured correctness run)
    static cudaStream_t s2 = []() {
        cudaStream_t s; cudaStreamCreateWithFlags(&s, cudaStreamNonBlocking); return s;
    }();
    static cudaEvent_t evA = []() {
        cudaEvent_t e; cudaEventCreateWithFlags(&e, cudaEventDisableTiming); return e;
    }();
    static cudaEvent_t evKV = []() {
        cudaEvent_t e; cudaEventCreateWithFlags(&e, cudaEventDisableTiming); return e;
    }();
    static cudaEvent_t evRB = []() {
        cudaEvent_t e; cudaEventCreateWithFlags(&e, cudaEventDisableTiming); return e;
    }();

    const float scale = 0.125f;  // 1/sqrt(64)
    const int M1 = DD * DD;

    const int smem128 = 2 * (128 + 128) * 36 * 4;   // 73728
    const int smemFA  = (4 * 64 + 128) * 68 * 4;    // 104448
    cudaFuncSetAttribute(gemm_tf32<128,0,0>, cudaFuncAttributeMaxDynamicSharedMemorySize, smem128);
    cudaFuncSetAttribute(gemm_tf32<128,0,1>, cudaFuncAttributeMaxDynamicSharedMemorySize, smem128);
    cudaFuncSetAttribute(gemm_tf32<128,1,0>, cudaFuncAttributeMaxDynamicSharedMemorySize, smem128);
    cudaFuncSetAttribute(gemm_tf32<128,2,0>, cudaFuncAttributeMaxDynamicSharedMemorySize, smem128);
    cudaFuncSetAttribute(flash_attn,         cudaFuncAttributeMaxDynamicSharedMemorySize, smemFA);

    // ===== round attention weights + inputs (critical path) =====
    roundA<<<dim3(1024, 6), 256>>>(
        (const float4*)sa_in_w,  (float4*)(wpr),        3*M1/4,
        (const float4*)sa_out_w, (float4*)(wpr + 3*M1), M1/4,
        (const float4*)ma_in_w,  (float4*)(wpr + 4*M1), 3*M1/4,
        (const float4*)ma_out_w, (float4*)(wpr + 7*M1), M1/4,
        (const float4*)tgt,      (float4*)tgtr,         NTOK*DD/4,
        (const float4*)memory,   (float4*)memr,         NTOK*DD/4);
    cudaEventRecord(evA, 0);

    // ===== side stream: cross-attn KV projection + MoE weight rounding =====
    cudaStreamWaitEvent(s2, evA, 0);
    gemm_tf32<128,0,1><<<dim3(2*DD/128, NTOK/128), 256, smem128, s2>>>(
        memr, DD, wpr + 5*M1, DD, ma_in_b + DD, kvx, 2*DD, DD, 1.f);
    cudaEventRecord(evKV, s2);
    roundB<<<dim3(4096, 2), 256, 0, s2>>>(
        (const float4*)w1, (float4*)w1r, (int)((size_t)EE*FF*DD/4),
        (const float4*)w2, (float4*)w2r, (int)((size_t)EE*DD*FF/4));
    cudaEventRecord(evRB, s2);

    // ===== Self-attention (main stream) =====
    gemm_tf32<128,0,1><<<dim3(3*DD/128, NTOK/128), 256, smem128>>>(tgtr, DD, wpr, DD, sa_in_b, qkv, 3*DD, DD, 1.f);
    flash_attn<<<dim3(SS/128, BB*HH), 256, smemFA>>>(qkv, 3*DD, qkv + DD, qkv + 2*DD, 3*DD, ctx, scale);
    gemm_tf32<128,0,0><<<dim3(DD/128, NTOK/128), 256, smem128>>>(ctx, DD, wpr + 3*M1, DD, sa_out_b, proj, DD, DD, 1.f);
    add_ln<<<NTOK, 256>>>(tgt, proj, ln1_g, ln1_b, x1, x1r);

    // ===== Cross-attention =====
    gemm_tf32<128,0,1><<<dim3(DD/128, NTOK/128), 256, smem128>>>(x1r, DD, wpr + 4*M1, DD, ma_in_b, qkv, DD, DD, 1.f);
    cudaStreamWaitEvent(0, evKV, 0);
    flash_attn<<<dim3(SS/128, BB*HH), 256, smemFA>>>(qkv, DD, kvx, kvx + DD, 2*DD, ctx, scale);
    gemm_tf32<128,0,0><<<dim3(DD/128, NTOK/128), 256, smem128>>>(ctx, DD, wpr + 7*M1, DD, ma_out_b, proj, DD, DD, 1.f);
    add_ln<<<NTOK, 256>>>(x1, proj, ln2_g, ln2_b, x2, x2r);

    // ===== MoE (sparse top-2) =====
    moe_init<<<1, 32>>>();
    router<<<NTOK, 128>>>(x2, wg, bg, wn, bn, noise);
    prefix_scatter<<<1, 256>>>();
    cudaStreamWaitEvent(0, evRB, 0);
    gemm_tf32<128,1,0><<<dim3(FF/128, NASSIGN/128, EE), 256, smem128>>>(x2r, 0, w1r, DD, b1, nullptr, 0, DD, 1.f);
    gemm_tf32<128,2,0><<<dim3(DD/128, NASSIGN/128, EE), 256, smem128>>>(hbuf, 0, w2r, FF, b2, nullptr, 0, FF, 1.f);
    moe_add_ln<<<NTOK, 256>>>(x2, ln3_g, ln3_b, (float*)d_out);
}

// round 16
// speedup vs baseline: 1.0554x; 1.0277x over previous
#include <cuda_runtime.h>
#include <math.h>
#include <stdint.h>

// Problem dims
#define BB 4
#define SS 1024
#define DD 1024
#define HH 16
#define HD 64
#define EE 16
#define FF 2048
#define NTOK (BB*SS)        // 4096
#define NASSIGN (NTOK*2)    // 8192

// ---------------- scratch (static device memory; no allocations) ----------------
__device__ __align__(256) float g_qkv[NTOK*3*DD];
__device__ __align__(256) float g_kvx[NTOK*2*DD];    // cross-attn K|V
__device__ __align__(256) float g_ctx[NTOK*DD];
__device__ __align__(256) float g_proj[NTOK*DD];
__device__ __align__(256) float g_x1[NTOK*DD];
__device__ __align__(256) float g_x2[NTOK*DD];
__device__ __align__(256) float g_x1r[NTOK*DD];
__device__ __align__(256) float g_x2r[NTOK*DD];
__device__ __align__(256) float g_h[(size_t)NASSIGN*FF];
__device__ __align__(256) float g_yb[(size_t)NASSIGN*DD];
// rounded weight / input copies
__device__ __align__(256) float g_w1r[(size_t)EE*FF*DD];
__device__ __align__(256) float g_w2r[(size_t)EE*DD*FF];
__device__ __align__(256) float g_wpr[8*DD*DD];
__device__ __align__(256) float g_tgtr[NTOK*DD];
__device__ __align__(256) float g_memr[NTOK*DD];
__device__ int   g_eidx[NASSIGN];
__device__ float g_gval[NASSIGN];
__device__ int   g_counts[EE];
__device__ int   g_off[EE];
__device__ int   g_fill[EE];
__device__ int   g_rowtok[NASSIGN];
__device__ float g_rowgate[NASSIGN];
__device__ int   g_arow[NASSIGN];
// MoE tile map: (expert, row-tile) pairs for non-empty 128-row tiles
#define MAXTILES 128
__device__ int   g_ntiles;
__device__ int   g_tmap_e[MAXTILES];
__device__ int   g_tmap_rt[MAXTILES];

// ---------------- helpers ----------------
__device__ __forceinline__ float rtf(float f) {
    uint32_t u;
    asm("cvt.rna.tf32.f32 %0, %1;" : "=r"(u) : "f"(f));
    return __uint_as_float(u);
}

__device__ __forceinline__ void mma8(float* c, const uint32_t* a, const uint32_t* b) {
    asm volatile(
        "mma.sync.aligned.m16n8k8.row.col.f32.tf32.tf32.f32 "
        "{%0,%1,%2,%3}, {%4,%5,%6,%7}, {%8,%9}, {%0,%1,%2,%3};"
        : "+f"(c[0]), "+f"(c[1]), "+f"(c[2]), "+f"(c[3])
        : "r"(a[0]), "r"(a[1]), "r"(a[2]), "r"(a[3]), "r"(b[0]), "r"(b[1]));
}

__device__ __forceinline__ void cp16(void* smem_dst, const void* gmem_src) {
    uint32_t d = (uint32_t)__cvta_generic_to_shared(smem_dst);
    asm volatile("cp.async.cg.shared.global [%0], [%1], 16;" :: "r"(d), "l"(gmem_src) : "memory");
}
__device__ __forceinline__ void cp_commit() {
    asm volatile("cp.async.commit_group;" ::: "memory");
}
__device__ __forceinline__ void cp_wait0() {
    asm volatile("cp.async.wait_group 0;" ::: "memory");
}

// ---------------- tf32 RN rounding: attention weights + inputs (6 segments) ----------------
__global__ __launch_bounds__(256) void roundA(
    const float4* s0, float4* d0, int n0,
    const float4* s1, float4* d1, int n1,
    const float4* s2, float4* d2, int n2,
    const float4* s3, float4* d3, int n3,
    const float4* s4, float4* d4, int n4,
    const float4* s5, float4* d5, int n5)
{
    const float4* src; float4* dst; int n4c;
    switch (blockIdx.y) {
        case 0: src = s0; dst = d0; n4c = n0; break;
        case 1: src = s1; dst = d1; n4c = n1; break;
        case 2: src = s2; dst = d2; n4c = n2; break;
        case 3: src = s3; dst = d3; n4c = n3; break;
        case 4: src = s4; dst = d4; n4c = n4; break;
        default: src = s5; dst = d5; n4c = n5; break;
    }
    for (int i = blockIdx.x * blockDim.x + threadIdx.x; i < n4c; i += gridDim.x * blockDim.x) {
        float4 v = src[i];
        v.x = rtf(v.x); v.y = rtf(v.y); v.z = rtf(v.z); v.w = rtf(v.w);
        dst[i] = v;
    }
}

// ---------------- tf32 RN rounding: MoE weights (2 segments) ----------------
__global__ __launch_bounds__(256) void roundB(
    const float4* s0, float4* d0, int n0,
    const float4* s1, float4* d1, int n1)
{
    const float4* src = blockIdx.y ? s1 : s0;
    float4* dst = blockIdx.y ? d1 : d0;
    int n4c = blockIdx.y ? n1 : n0;
    for (int i = blockIdx.x * blockDim.x + threadIdx.x; i < n4c; i += gridDim.x * blockDim.x) {
        float4 v = src[i];
        v.x = rtf(v.x); v.y = rtf(v.y); v.z = rtf(v.z); v.w = rtf(v.w);
        dst[i] = v;
    }
}

// ================= fused flash attention (tf32 MMA, cp.async double-buffered K/V) =================
__global__ __launch_bounds__(256) void flash_attn(
    const float* __restrict__ Q, int ldq,
    const float* __restrict__ Kp, const float* __restrict__ Vp, int ldkv,
    float* __restrict__ O, float scale)
{
    extern __shared__ float fsm[];
    float (*Ks)[68] = (float(*)[68])fsm;                   // [2*64][68] key-major
    float (*Vs)[68] = (float(*)[68])(fsm + 2*64*68);       // [2*64][68] key-major
    float (*Ps)[68] = (float(*)[68])(fsm + 4*64*68);       // [128][68]

    const int tid = threadIdx.x, warp = tid >> 5, lane = tid & 31;
    const int gr = lane >> 2, qd = lane & 3;
    const int z = blockIdx.y, b = z >> 4, h = z & 15;
    const int q0 = blockIdx.x * 128;
    const float* Qb = Q  + (size_t)(b * SS + q0) * ldq  + h * HD;
    const float* Kb = Kp + (size_t)(b * SS) * ldkv + h * HD;
    const float* Vb = Vp + (size_t)(b * SS) * ldkv + h * HD;

    int lrow[4], lcol[4];
#pragma unroll
    for (int i = 0; i < 4; i++) {
        int f4 = i * 256 + tid;
        lrow[i] = f4 >> 4;
        lcol[i] = (f4 & 15) * 4;
    }

#pragma unroll
    for (int i = 0; i < 8; i++) {
        int f4 = i * 256 + tid;
        int r = f4 >> 4, c = (f4 & 15) * 4;
        *(float4*)&Ps[r][c] = *(const float4*)(Qb + (size_t)r * ldq + c);
    }
    __syncthreads();
    uint32_t qf[8][4];
    const int r0 = warp * 16 + gr;
#pragma unroll
    for (int ks = 0; ks < 8; ks++) {
        qf[ks][0] = __float_as_uint(Ps[r0][ks*8 + qd]);
        qf[ks][1] = __float_as_uint(Ps[r0+8][ks*8 + qd]);
        qf[ks][2] = __float_as_uint(Ps[r0][ks*8 + qd + 4]);
        qf[ks][3] = __float_as_uint(Ps[r0+8][ks*8 + qd + 4]);
    }
    __syncthreads();

    float of[8][4];
#pragma unroll
    for (int nt = 0; nt < 8; nt++) { of[nt][0]=of[nt][1]=of[nt][2]=of[nt][3]=0.f; }
    float m0 = -1e30f, m1 = -1e30f, l0 = 0.f, l1 = 0.f;

#pragma unroll
    for (int i = 0; i < 4; i++) {
        cp16(&Ks[lrow[i]][lcol[i]], Kb + (size_t)lrow[i] * ldkv + lcol[i]);
        cp16(&Vs[lrow[i]][lcol[i]], Vb + (size_t)lrow[i] * ldkv + lcol[i]);
    }
    cp_commit();

    for (int kt = 0; kt < SS / 64; kt++) {
        const int buf = (kt & 1) * 64;
        cp_wait0();
        __syncthreads();

        if (kt + 1 < SS / 64) {
            const int nbuf = ((kt + 1) & 1) * 64;
            const size_t kbase = (size_t)((kt + 1) * 64);
#pragma unroll
            for (int i = 0; i < 4; i++) {
                cp16(&Ks[nbuf + lrow[i]][lcol[i]], Kb + (kbase + lrow[i]) * ldkv + lcol[i]);
                cp16(&Vs[nbuf + lrow[i]][lcol[i]], Vb + (kbase + lrow[i]) * ldkv + lcol[i]);
            }
        }
        cp_commit();

        float sf[8][4];
#pragma unroll
        for (int nt = 0; nt < 8; nt++) { sf[nt][0]=sf[nt][1]=sf[nt][2]=sf[nt][3]=0.f; }
#pragma unroll
        for (int ks = 0; ks < 8; ks++) {
#pragma unroll
            for (int nt = 0; nt < 8; nt++) {
                uint32_t bf[2];
                int nr = nt * 8 + gr;
                bf[0] = __float_as_uint(Ks[buf + nr][ks*8 + qd]);
                bf[1] = __float_as_uint(Ks[buf + nr][ks*8 + qd + 4]);
                mma8(sf[nt], qf[ks], bf);
            }
        }

        float tm0 = -1e30f, tm1 = -1e30f;
#pragma unroll
        for (int nt = 0; nt < 8; nt++) {
            sf[nt][0] *= scale; sf[nt][1] *= scale; sf[nt][2] *= scale; sf[nt][3] *= scale;
            tm0 = fmaxf(tm0, fmaxf(sf[nt][0], sf[nt][1]));
            tm1 = fmaxf(tm1, fmaxf(sf[nt][2], sf[nt][3]));
        }
        tm0 = fmaxf(tm0, __shfl_xor_sync(~0u, tm0, 1));
        tm0 = fmaxf(tm0, __shfl_xor_sync(~0u, tm0, 2));
        tm1 = fmaxf(tm1, __shfl_xor_sync(~0u, tm1, 1));
        tm1 = fmaxf(tm1, __shfl_xor_sync(~0u, tm1, 2));
        const float mn0 = fmaxf(m0, tm0), mn1 = fmaxf(m1, tm1);
        const float a0 = __expf(m0 - mn0), a1 = __expf(m1 - mn1);
        float ts0 = 0.f, ts1 = 0.f;
#pragma unroll
        for (int nt = 0; nt < 8; nt++) {
            float p0 = __expf(sf[nt][0] - mn0), p1 = __expf(sf[nt][1] - mn0);
            float p2 = __expf(sf[nt][2] - mn1), p3 = __expf(sf[nt][3] - mn1);
            ts0 += p0 + p1; ts1 += p2 + p3;
            int cn = nt * 8 + 2 * qd;
            Ps[r0][cn] = rtf(p0);   Ps[r0][cn+1] = rtf(p1);
            Ps[r0+8][cn] = rtf(p2); Ps[r0+8][cn+1] = rtf(p3);
        }
        ts0 += __shfl_xor_sync(~0u, ts0, 1); ts0 += __shfl_xor_sync(~0u, ts0, 2);
        ts1 += __shfl_xor_sync(~0u, ts1, 1); ts1 += __shfl_xor_sync(~0u, ts1, 2);
        l0 = a0 * l0 + ts0; l1 = a1 * l1 + ts1;
        m0 = mn0; m1 = mn1;
#pragma unroll
        for (int nt = 0; nt < 8; nt++) {
            of[nt][0] *= a0; of[nt][1] *= a0; of[nt][2] *= a1; of[nt][3] *= a1;
        }
        __syncwarp();

#pragma unroll
        for (int ks = 0; ks < 8; ks++) {
            uint32_t af[4];
            af[0] = __float_as_uint(Ps[r0][ks*8 + qd]);
            af[1] = __float_as_uint(Ps[r0+8][ks*8 + qd]);
            af[2] = __float_as_uint(Ps[r0][ks*8 + qd + 4]);
            af[3] = __float_as_uint(Ps[r0+8][ks*8 + qd + 4]);
#pragma unroll
            for (int nt = 0; nt < 8; nt++) {
                uint32_t bf[2];
                int nr = nt * 8 + gr;
                bf[0] = __float_as_uint(Vs[buf + ks*8 + qd][nr]);
                bf[1] = __float_as_uint(Vs[buf + ks*8 + qd + 4][nr]);
                mma8(of[nt], af, bf);
            }
        }
    }

    const float il0 = 1.f / l0, il1 = 1.f / l1;
    float* Ob = O + (size_t)(b * SS + q0) * DD + h * HD;
#pragma unroll
    for (int nt = 0; nt < 8; nt++) {
        int cn = nt * 8 + 2 * qd;
        float2 o0 = { rtf(of[nt][0] * il0), rtf(of[nt][1] * il0) };
        float2 o1 = { rtf(of[nt][2] * il1), rtf(of[nt][3] * il1) };
        *(float2*)(Ob + (size_t)r0 * DD + cn) = o0;
        *(float2*)(Ob + (size_t)(r0 + 8) * DD + cn) = o1;
    }
}

// ================= unified tf32 GEMM (2-stage cp.async, single barrier/iter) =================
// BM=128, BN=128, 8 warps 4(m)x2(n), warp tile 32x64. 2 CTAs/SM.
// MODE 0: projection (ROUND=1 rounds output). MODE 1/2: MoE via tile map.
template<int BN, int MODE, int ROUND = 0>
__global__ __launch_bounds__(256, 2) void gemm_tf32(
    const float* __restrict__ A, int lda,
    const float* __restrict__ Bg, int ldb,
    const float* __restrict__ bias,
    float* __restrict__ C, int ldc,
    int K, float scale)
{
    constexpr int NT  = BN / 16;
    constexpr int BF4 = BN * 32 / 4 / 256;
    extern __shared__ uint32_t smem_[];
    uint32_t (*As)[36] = (uint32_t(*)[36])smem_;
    uint32_t (*Bs)[36] = (uint32_t(*)[36])(smem_ + 2 * 128 * 36);

    const int tid = threadIdx.x;
    const int warp = tid >> 5, lane = tid & 31;
    const int gr = lane >> 2, qd = lane & 3;
    const int m_base = (warp >> 1) * 32;
    const int n_base = (warp & 1) * (BN / 2);
    const int bn = blockIdx.x * BN;

    int bm, zb;
    if constexpr (MODE == 1 || MODE == 2) {
        int ty = blockIdx.y;
        if (ty >= g_ntiles) return;
        zb = g_tmap_e[ty];
        bm = g_tmap_rt[ty] * 128;
    } else {
        bm = blockIdx.y * 128;
        zb = 0;
    }

    int count = 0, base = 0, rt = 0;
    const float* biasp = nullptr;
    const float* Bbase = nullptr;
    float* Cb = nullptr;

    if constexpr (MODE == 1) {
        count = g_counts[zb]; rt = bm; base = g_off[zb];
        Bbase = Bg + (size_t)zb * FF * DD + (size_t)bn * DD;
        biasp = bias + (size_t)zb * FF + bn;
    } else if constexpr (MODE == 2) {
        count = g_counts[zb]; rt = bm; base = g_off[zb];
        Bbase = Bg + (size_t)zb * DD * FF + (size_t)bn * FF;
        biasp = bias + (size_t)zb * DD + bn;
    } else {
        Bbase = Bg + (size_t)bn * ldb;
        biasp = bias ? bias + bn : nullptr;
        Cb = C + (size_t)bm * ldc + bn;
    }

    const int ldb_eff = (MODE == 1) ? DD : (MODE == 2) ? FF : ldb;

    const float* aptr[4];
    int arow[4], acol[4];
#pragma unroll
    for (int i = 0; i < 4; i++) {
        int f4 = i * 256 + tid;
        int r = f4 >> 3, c = (f4 & 7) * 4;
        arow[i] = r; acol[i] = c;
        if constexpr (MODE == 1) {
            int rr = rt + r; if (rr > count - 1) rr = count - 1;
            aptr[i] = A + (size_t)g_rowtok[base + rr] * DD + c;
        } else if constexpr (MODE == 2) {
            int rr = rt + r; if (rr > count - 1) rr = count - 1;
            aptr[i] = A + (size_t)(base + rr) * FF + c;
        } else {
            aptr[i] = A + (size_t)(bm + r) * lda + c;
        }
    }

    const float* bptr[BF4];
    int brow[BF4], bcol[BF4];
#pragma unroll
    for (int i = 0; i < BF4; i++) {
        int f4 = i * 256 + tid;
        int r = f4 >> 3, c = (f4 & 7) * 4;
        brow[i] = r; bcol[i] = c;
        bptr[i] = Bbase + (size_t)r * ldb_eff + c;
    }

    float cf[2][NT][4];
#pragma unroll
    for (int mt = 0; mt < 2; mt++)
#pragma unroll
        for (int nt = 0; nt < NT; nt++)
#pragma unroll
            for (int j = 0; j < 4; j++) cf[mt][nt][j] = 0.f;

    const int nIter = K >> 5;

    // prologue: stage 0
#pragma unroll
    for (int i = 0; i < 4; i++)
        cp16(&As[arow[i]][acol[i]], aptr[i]);
#pragma unroll
    for (int i = 0; i < BF4; i++)
        cp16(&Bs[brow[i]][bcol[i]], bptr[i]);
    cp_commit();

    for (int it = 0; it < nIter; it++) {
        const int buf = it & 1;
        cp_wait0();
        __syncthreads();   // stage it visible; reads of stage it-1 done in all warps

        if (it + 1 < nIter) {
            const int nbuf = buf ^ 1;
            const int k0 = (it + 1) << 5;
#pragma unroll
            for (int i = 0; i < 4; i++)
                cp16(&As[nbuf * 128 + arow[i]][acol[i]], aptr[i] + k0);
#pragma unroll
            for (int i = 0; i < BF4; i++)
                cp16(&Bs[nbuf * BN + brow[i]][bcol[i]], bptr[i] + k0);
        }
        cp_commit();

        const uint32_t (*A_)[36] = (const uint32_t(*)[36])&As[buf * 128];
        const uint32_t (*B_)[36] = (const uint32_t(*)[36])&Bs[buf * BN];
#pragma unroll
        for (int kk = 0; kk < 32; kk += 8) {
            uint32_t af[2][4];
#pragma unroll
            for (int mt = 0; mt < 2; mt++) {
                int r0 = m_base + mt * 16 + gr;
                af[mt][0] = A_[r0][kk + qd];
                af[mt][1] = A_[r0 + 8][kk + qd];
                af[mt][2] = A_[r0][kk + qd + 4];
                af[mt][3] = A_[r0 + 8][kk + qd + 4];
            }
#pragma unroll
            for (int nt = 0; nt < NT; nt++) {
                uint32_t bf[2];
                int nr = n_base + nt * 8 + gr;
                bf[0] = B_[nr][kk + qd];
                bf[1] = B_[nr][kk + qd + 4];
#pragma unroll
                for (int mt = 0; mt < 2; mt++) mma8(cf[mt][nt], af[mt], bf);
            }
        }
    }

#pragma unroll
    for (int mt = 0; mt < 2; mt++) {
#pragma unroll
        for (int half = 0; half < 2; half++) {
            int lr = m_base + mt * 16 + gr + half * 8;
#pragma unroll
            for (int nt = 0; nt < NT; nt++) {
                int cn = n_base + nt * 8 + qd * 2;
                float v0 = cf[mt][nt][half * 2 + 0];
                float v1 = cf[mt][nt][half * 2 + 1];
                if constexpr (MODE == 0) {
                    float b0 = biasp ? biasp[cn] : 0.f;
                    float b1 = biasp ? biasp[cn + 1] : 0.f;
                    float o0 = v0 * scale + b0, o1 = v1 * scale + b1;
                    if constexpr (ROUND) { o0 = rtf(o0); o1 = rtf(o1); }
                    float2 o = {o0, o1};
                    *(float2*)(Cb + (size_t)lr * ldc + cn) = o;
                } else if constexpr (MODE == 1) {
                    int grow = rt + lr;
                    if (grow < count) {
                        float* p = g_h + (size_t)(base + grow) * FF + bn + cn;
                        p[0] = rtf(fmaxf(v0 + biasp[cn], 0.f));
                        p[1] = rtf(fmaxf(v1 + biasp[cn + 1], 0.f));
                    }
                } else { // MODE == 2
                    int grow = rt + lr;
                    if (grow < count) {
                        float gate = g_rowgate[base + grow];
                        float* p = g_yb + (size_t)(base + grow) * DD + bn + cn;
                        p[0] = gate * (v0 + biasp[cn]);
                        p[1] = gate * (v1 + biasp[cn + 1]);
                    }
                }
            }
        }
    }
}

// ---------------- fused residual add + LayerNorm (+ optional rounded copy) ----------------
__global__ __launch_bounds__(256) void add_ln(
    const float* __restrict__ X, const float* __restrict__ Y,
    const float* __restrict__ gam, const float* __restrict__ bet,
    float* __restrict__ O, float* __restrict__ Or)
{
    __shared__ float red[256];
    const int t = blockIdx.x, tid = threadIdx.x;
    const float* x = X + (size_t)t * DD;
    const float* y = Y + (size_t)t * DD;
    float v[4]; float s = 0.f;
#pragma unroll
    for (int i = 0; i < 4; i++) { v[i] = x[tid + i * 256] + y[tid + i * 256]; s += v[i]; }
    red[tid] = s; __syncthreads();
    for (int st = 128; st > 0; st >>= 1) { if (tid < st) red[tid] += red[tid + st]; __syncthreads(); }
    const float mean = red[0] * (1.f / 1024.f);
    __syncthreads();
    float s2 = 0.f;
#pragma unroll
    for (int i = 0; i < 4; i++) { float d = v[i] - mean; s2 += d * d; }
    red[tid] = s2; __syncthreads();
    for (int st = 128; st > 0; st >>= 1) { if (tid < st) red[tid] += red[tid + st]; __syncthreads(); }
    const float inv = rsqrtf(red[0] * (1.f / 1024.f) + 1e-5f);
    float* o = O + (size_t)t * DD;
    float* orr = Or ? Or + (size_t)t * DD : nullptr;
#pragma unroll
    for (int i = 0; i < 4; i++) {
        int idx = tid + i * 256;
        float val = (v[i] - mean) * inv * gam[idx] + bet[idx];
        o[idx] = val;
        if (orr) orr[idx] = rtf(val);
    }
}

// ---------------- MoE router: noisy top-2 ----------------
__global__ void moe_init()
{
    if (threadIdx.x < EE) { g_counts[threadIdx.x] = 0; g_fill[threadIdx.x] = 0; }
}

__global__ __launch_bounds__(128) void router(
    const float* __restrict__ X,
    const float* __restrict__ wg, const float* __restrict__ bg,
    const float* __restrict__ wn, const float* __restrict__ bn,
    const float* __restrict__ eps)
{
    __shared__ float xs[1024];
    __shared__ float lg[32];
    const int t = blockIdx.x, tid = threadIdx.x;
    const float* x = X + (size_t)t * DD;
    for (int i = tid; i < 1024; i += 128) xs[i] = x[i];
    __syncthreads();
    const int warp = tid >> 5, lane = tid & 31;
    for (int dd = warp * 8; dd < warp * 8 + 8; dd++) {
        const float* w = (dd < 16) ? (wg + (size_t)dd * DD) : (wn + (size_t)(dd - 16) * DD);
        float s = 0.f;
        for (int i = lane; i < 1024; i += 32) s += xs[i] * w[i];
#pragma unroll
        for (int o = 16; o; o >>= 1) s += __shfl_xor_sync(0xffffffffu, s, o);
        if (lane == 0) lg[dd] = s;
    }
    __syncthreads();
    if (tid == 0) {
        float nv[16];
#pragma unroll
        for (int e = 0; e < 16; e++) {
            float gz = lg[e] + bg[e];
            float nz = lg[16 + e] + bn[e];
            float sp = (nz > 0.f) ? (nz + log1pf(expf(-nz))) : log1pf(expf(nz));
            nv[e] = gz + eps[(size_t)t * EE + e] * sp;
        }
        int i0 = 0; float v0 = nv[0];
        for (int e = 1; e < 16; e++) if (nv[e] > v0) { v0 = nv[e]; i0 = e; }
        int i1 = (i0 == 0) ? 1 : 0; float v1 = nv[i1];
        for (int e = 0; e < 16; e++) { if (e == i0) continue; if (nv[e] > v1) { v1 = nv[e]; i1 = e; } }
        float g0 = 1.f / (1.f + expf(v1 - v0));
        float g1 = 1.f - g0;
        g_eidx[2 * t] = i0; g_eidx[2 * t + 1] = i1;
        g_gval[2 * t] = g0; g_gval[2 * t + 1] = g1;
        atomicAdd(&g_counts[i0], 1);
        atomicAdd(&g_counts[i1], 1);
    }
}

// ---------------- fused prefix + tile map + scatter (one block) ----------------
__global__ __launch_bounds__(256) void prefix_scatter()
{
    const int tid = threadIdx.x;
    if (tid == 0) {
        int s = 0, tt = 0;
        for (int e = 0; e < EE; e++) {
            g_off[e] = s;
            int cnt = g_counts[e];
            int nt_ = (cnt + 127) >> 7;
            for (int k = 0; k < nt_ && tt < MAXTILES; k++) {
                g_tmap_e[tt] = e;
                g_tmap_rt[tt] = k;
                tt++;
            }
            s += cnt;
        }
        g_ntiles = tt;
    }
    __syncthreads();
    for (int i = tid; i < NASSIGN; i += 256) {
        int e = g_eidx[i];
        int pos = atomicAdd(&g_fill[e], 1);
        int row = g_off[e] + pos;
        g_rowtok[row] = i >> 1;
        g_rowgate[row] = g_gval[i];
        g_arow[i] = row;
    }
}

// ---------------- final: out = LN3(x2 + yb[r0] + yb[r1]) ----------------
__global__ __launch_bounds__(256) void moe_add_ln(
    const float* __restrict__ X,
    const float* __restrict__ gam, const float* __restrict__ bet,
    float* __restrict__ O)
{
    __shared__ float red[256];
    const int t = blockIdx.x, tid = threadIdx.x;
    const int r0 = g_arow[2 * t], r1 = g_arow[2 * t + 1];
    const float* x = X + (size_t)t * DD;
    const float* y0 = g_yb + (size_t)r0 * DD;
    const float* y1 = g_yb + (size_t)r1 * DD;
    float v[4]; float s = 0.f;
#pragma unroll
    for (int i = 0; i < 4; i++) {
        int idx = tid + i * 256;
        v[i] = x[idx] + y0[idx] + y1[idx];
        s += v[i];
    }
    red[tid] = s; __syncthreads();
    for (int st = 128; st > 0; st >>= 1) { if (tid < st) red[tid] += red[tid + st]; __syncthreads(); }
    const float mean = red[0] * (1.f / 1024.f);
    __syncthreads();
    float s2 = 0.f;
#pragma unroll
    for (int i = 0; i < 4; i++) { float d = v[i] - mean; s2 += d * d; }
    red[tid] = s2; __syncthreads();
    for (int st = 128; st > 0; st >>= 1) { if (tid < st) red[tid] += red[tid + st]; __syncthreads(); }
    const float inv = rsqrtf(red[0] * (1.f / 1024.f) + 1e-5f);
    float* o = O + (size_t)t * DD;
#pragma unroll
    for (int i = 0; i < 4; i++) {
        int idx = tid + i * 256;
        o[idx] = (v[i] - mean) * inv * gam[idx] + bet[idx];
    }
}

// ---------------- host launch ----------------
extern "C" void kernel_launch(void* const* d_in, const int* in_sizes, int n_in,
                              void* d_out, int out_size)
{
    const float* tgt      = (const float*)d_in[0];
    const float* memory   = (const float*)d_in[1];
    const float* noise    = (const float*)d_in[2];
    const float* sa_in_w  = (const float*)d_in[3];
    const float* sa_in_b  = (const float*)d_in[4];
    const float* sa_out_w = (const float*)d_in[5];
    const float* sa_out_b = (const float*)d_in[6];
    const float* ma_in_w  = (const float*)d_in[7];
    const float* ma_in_b  = (const float*)d_in[8];
    const float* ma_out_w = (const float*)d_in[9];
    const float* ma_out_b = (const float*)d_in[10];
    const float* wg       = (const float*)d_in[11];
    const float* bg       = (const float*)d_in[12];
    const float* wn       = (const float*)d_in[13];
    const float* bn       = (const float*)d_in[14];
    const float* w1       = (const float*)d_in[15];
    const float* b1       = (const float*)d_in[16];
    const float* w2       = (const float*)d_in[17];
    const float* b2       = (const float*)d_in[18];
    const float* ln1_g    = (const float*)d_in[19];
    const float* ln1_b    = (const float*)d_in[20];
    const float* ln2_g    = (const float*)d_in[21];
    const float* ln2_b    = (const float*)d_in[22];
    const float* ln3_g    = (const float*)d_in[23];
    const float* ln3_b    = (const float*)d_in[24];

    float *qkv, *kvx, *ctx, *proj, *x1, *x2, *x1r, *x2r, *hbuf;
    float *w1r, *w2r, *wpr, *tgtr, *memr;
    cudaGetSymbolAddress((void**)&qkv,    g_qkv);
    cudaGetSymbolAddress((void**)&kvx,    g_kvx);
    cudaGetSymbolAddress((void**)&ctx,    g_ctx);
    cudaGetSymbolAddress((void**)&proj,   g_proj);
    cudaGetSymbolAddress((void**)&x1,     g_x1);
    cudaGetSymbolAddress((void**)&x2,     g_x2);
    cudaGetSymbolAddress((void**)&x1r,    g_x1r);
    cudaGetSymbolAddress((void**)&x2r,    g_x2r);
    cudaGetSymbolAddress((void**)&hbuf,   g_h);
    cudaGetSymbolAddress((void**)&w1r,    g_w1r);
    cudaGetSymbolAddress((void**)&w2r,    g_w2r);
    cudaGetSymbolAddress((void**)&wpr,    g_wpr);
    cudaGetSymbolAddress((void**)&tgtr,   g_tgtr);
    cudaGetSymbolAddress((void**)&memr,   g_memr);

    // one-time stream/event creation (first call = uncaptured correctness run)
    static cudaStream_t s2 = []() {
        cudaStream_t s; cudaStreamCreateWithFlags(&s, cudaStreamNonBlocking); return s;
    }();
    static cudaEvent_t evA = []() {
        cudaEvent_t e; cudaEventCreateWithFlags(&e, cudaEventDisableTiming); return e;
    }();
    static cudaEvent_t evKV = []() {
        cudaEvent_t e; cudaEventCreateWithFlags(&e, cudaEventDisableTiming); return e;
    }();
    static cudaEvent_t evRB = []() {
        cudaEvent_t e; cudaEventCreateWithFlags(&e, cudaEventDisableTiming); return e;
    }();

    const float scale = 0.125f;  // 1/sqrt(64)
    const int M1 = DD * DD;

    const int smem128 = 2 * (128 + 128) * 36 * 4;   // 73728
    const int smemFA  = (4 * 64 + 128) * 68 * 4;    // 104448
    cudaFuncSetAttribute(gemm_tf32<128,0,0>, cudaFuncAttributeMaxDynamicSharedMemorySize, smem128);
    cudaFuncSetAttribute(gemm_tf32<128,0,1>, cudaFuncAttributeMaxDynamicSharedMemorySize, smem128);
    cudaFuncSetAttribute(gemm_tf32<128,1,0>, cudaFuncAttributeMaxDynamicSharedMemorySize, smem128);
    cudaFuncSetAttribute(gemm_tf32<128,2,0>, cudaFuncAttributeMaxDynamicSharedMemorySize, smem128);
    cudaFuncSetAttribute(flash_attn,         cudaFuncAttributeMaxDynamicSharedMemorySize, smemFA);

    // ===== round attention weights + inputs (critical path) =====
    roundA<<<dim3(1024, 6), 256>>>(
        (const float4*)sa_in_w,  (float4*)(wpr),        3*M1/4,
        (const float4*)sa_out_w, (float4*)(wpr + 3*M1), M1/4,
        (const float4*)ma_in_w,  (float4*)(wpr + 4*M1), 3*M1/4,
        (const float4*)ma_out_w, (float4*)(wpr + 7*M1), M1/4,
        (const float4*)tgt,      (float4*)tgtr,         NTOK*DD/4,
        (const float4*)memory,   (float4*)memr,         NTOK*DD/4);
    cudaEventRecord(evA, 0);

    // ===== side stream: cross-attn KV projection + MoE weight rounding =====
    cudaStreamWaitEvent(s2, evA, 0);
    gemm_tf32<128,0,1><<<dim3(2*DD/128, NTOK/128), 256, smem128, s2>>>(
        memr, DD, wpr + 5*M1, DD, ma_in_b + DD, kvx, 2*DD, DD, 1.f);
    cudaEventRecord(evKV, s2);
    roundB<<<dim3(4096, 2), 256, 0, s2>>>(
        (const float4*)w1, (float4*)w1r, (int)((size_t)EE*FF*DD/4),
        (const float4*)w2, (float4*)w2r, (int)((size_t)EE*DD*FF/4));
    cudaEventRecord(evRB, s2);

    // ===== Self-attention (main stream) =====
    gemm_tf32<128,0,1><<<dim3(3*DD/128, NTOK/128), 256, smem128>>>(tgtr, DD, wpr, DD, sa_in_b, qkv, 3*DD, DD, 1.f);
    flash_attn<<<dim3(SS/128, BB*HH), 256, smemFA>>>(qkv, 3*DD, qkv + DD, qkv + 2*DD, 3*DD, ctx, scale);
    gemm_tf32<128,0,0><<<dim3(DD/128, NTOK/128), 256, smem128>>>(ctx, DD, wpr + 3*M1, DD, sa_out_b, proj, DD, DD, 1.f);
    add_ln<<<NTOK, 256>>>(tgt, proj, ln1_g, ln1_b, x1, x1r);

    // ===== Cross-attention =====
    gemm_tf32<128,0,1><<<dim3(DD/128, NTOK/128), 256, smem128>>>(x1r, DD, wpr + 4*M1, DD, ma_in_b, qkv, DD, DD, 1.f);
    cudaStreamWaitEvent(0, evKV, 0);
    flash_attn<<<dim3(SS/128, BB*HH), 256, smemFA>>>(qkv, DD, kvx, kvx + DD, 2*DD, ctx, scale);
    gemm_tf32<128,0,0><<<dim3(DD/128, NTOK/128), 256, smem128>>>(ctx, DD, wpr + 7*M1, DD, ma_out_b, proj, DD, DD, 1.f);
    add_ln<<<NTOK, 256>>>(x1, proj, ln2_g, ln2_b, x2, x2r);

    // ===== MoE (sparse top-2) =====
    moe_init<<<1, 32>>>();
    router<<<NTOK, 128>>>(x2, wg, bg, wn, bn, noise);
    prefix_scatter<<<1, 256>>>();
    cudaStreamWaitEvent(0, evRB, 0);
    gemm_tf32<128,1,0><<<dim3(FF/128, MAXTILES), 256, smem128>>>(x2r, 0, w1r, DD, b1, nullptr, 0, DD, 1.f);
    gemm_tf32<128,2,0><<<dim3(DD/128, MAXTILES), 256, smem128>>>(hbuf, 0, w2r, FF, b2, nullptr, 0, FF, 1.f);
    moe_add_ln<<<NTOK, 256>>>(x2, ln3_g, ln3_b, (float*)d_out);
}